// round 8
// baseline (speedup 1.0000x reference)
#include <cuda_runtime.h>
#include <cuda_fp16.h>
#include <cstdint>

// Problem constants (fixed by the dataset)
#define NN    50000
#define EE    800000
#define IN_F  96
#define HID_F 128
#define OUT_F 64
#define TT    8

#define SCAN_BLK 512
#define NBLK ((NN + SCAN_BLK - 1) / SCAN_BLK)    // 98

// ---------------- static device scratch (no allocations allowed) -------------
__device__ int      g_counts[NN];      // zero-init at load; re-zeroed by k_scan23
__device__ int      g_rowptr[NN + 1];
__device__ int      g_cursor[NN];
__device__ int      g_bsum[NBLK];
__device__ int2     g_epack[EE];                            // (src, w-as-bits)
__device__ __half   g_xh[(size_t)NN * IN_F];                // 9.6 MB fp16 x
__device__ __half   g_ph[(size_t)NN * TT * OUT_F];          // 51.2 MB, [n][t*64+c]
__device__ uint32_t g_B1h[TT * HID_F * 48];                 // fp16x2 [t][n][k2]
__device__ uint32_t g_B2h[TT * OUT_F * 64];                 // fp16x2 [t][n][k2]

// ---------------- helpers ------------------------------------------------------
__device__ __forceinline__ void mma_f16(float d[4],
                                        uint32_t a0, uint32_t a1, uint32_t a2, uint32_t a3,
                                        uint32_t b0, uint32_t b1) {
    asm volatile("mma.sync.aligned.m16n8k16.row.col.f32.f16.f16.f32 "
        "{%0,%1,%2,%3}, {%4,%5,%6,%7}, {%8,%9}, {%0,%1,%2,%3};"
        : "+f"(d[0]), "+f"(d[1]), "+f"(d[2]), "+f"(d[3])
        : "r"(a0), "r"(a1), "r"(a2), "r"(a3), "r"(b0), "r"(b1));
}
__device__ __forceinline__ uint32_t pack_h2(float a, float b) {
    __half2 h = __float22half2_rn(make_float2(a, b));
    return *(uint32_t*)&h;
}

// ---------------- CSR build --------------------------------------------------
__global__ void k_hist(const int4* __restrict__ dst4) {
    int i = blockIdx.x * blockDim.x + threadIdx.x;
    if (i < EE / 4) {
        int4 d = dst4[i];
        atomicAdd(&g_counts[d.x], 1);
        atomicAdd(&g_counts[d.y], 1);
        atomicAdd(&g_counts[d.z], 1);
        atomicAdd(&g_counts[d.w], 1);
    }
}
__global__ void k_scan1() {
    __shared__ int s[SCAN_BLK];
    int b = blockIdx.x, tid = threadIdx.x;
    int i = b * SCAN_BLK + tid;
    s[tid] = (i < NN) ? g_counts[i] : 0;
    __syncthreads();
    #pragma unroll
    for (int off = SCAN_BLK / 2; off > 0; off >>= 1) {
        if (tid < off) s[tid] += s[tid + off];
        __syncthreads();
    }
    if (tid == 0) g_bsum[b] = s[0];
}
// combined: per-block redundant scan of the 98 block sums + local scan
__global__ void k_scan23() {
    __shared__ int s[SCAN_BLK];
    __shared__ int bs[128];
    __shared__ int boff;
    int b = blockIdx.x, tid = threadIdx.x;
    int i = b * SCAN_BLK + tid;
    int c = (i < NN) ? g_counts[i] : 0;
    s[tid] = c;
    if (tid < 128) bs[tid] = (tid < NBLK) ? g_bsum[tid] : 0;
    __syncthreads();
    if (tid < 128) {
        #pragma unroll
        for (int off = 1; off < 128; off <<= 1) {
            int u = (tid >= off) ? bs[tid - off] : 0;
            __syncthreads();
            bs[tid] += u;
            __syncthreads();
        }
        if (tid == 0) boff = (b == 0) ? 0 : bs[b - 1];
    } else {
        #pragma unroll
        for (int off = 1; off < 128; off <<= 1) { __syncthreads(); __syncthreads(); }
    }
    __syncthreads();
    #pragma unroll
    for (int off = 1; off < SCAN_BLK; off <<= 1) {
        int u = (tid >= off) ? s[tid - off] : 0;
        __syncthreads();
        s[tid] += u;
        __syncthreads();
    }
    if (i < NN) {
        int excl = s[tid] - c + boff;
        g_rowptr[i] = excl;
        g_cursor[i] = excl;
        g_counts[i] = 0;                      // restore invariant for next call
        if (i == NN - 1) g_rowptr[NN] = excl + c;
    }
}
__global__ void k_scatter(const int4* __restrict__ src4, const int4* __restrict__ dst4,
                          const float4* __restrict__ ew4) {
    int i = blockIdx.x * blockDim.x + threadIdx.x;
    if (i >= EE / 4) return;
    int4   s = src4[i];
    int4   d = dst4[i];
    float4 w = ew4[i];
    int p0 = atomicAdd(&g_cursor[d.x], 1);
    int p1 = atomicAdd(&g_cursor[d.y], 1);
    int p2 = atomicAdd(&g_cursor[d.z], 1);
    int p3 = atomicAdd(&g_cursor[d.w], 1);
    g_epack[p0] = make_int2(s.x, __float_as_int(w.x));
    g_epack[p1] = make_int2(s.y, __float_as_int(w.y));
    g_epack[p2] = make_int2(s.z, __float_as_int(w.z));
    g_epack[p3] = make_int2(s.w, __float_as_int(w.w));
}

// ---------------- convert: x->fp16 AND masked weights -> fp16x2 ----------------
#define XW (NN * IN_F / 2)                 // 2,400,000 half2
__global__ void k_convert(const float* __restrict__ x,
                          const float* __restrict__ W1, const float* __restrict__ W2,
                          const float* __restrict__ M1, const float* __restrict__ M2) {
    int i = blockIdx.x * blockDim.x + threadIdx.x;
    if (i < XW) {
        float2 v = *(const float2*)(x + i * 2);
        *((__half2*)g_xh + i) = __float22half2_rn(v);
    }
    const int S1 = TT * HID_F * 48;        // 49152
    const int S2 = TT * OUT_F * 64;        // 32768
    if (i < S1) {
        int t = i / (HID_F * 48);
        int rem = i % (HID_F * 48);
        int n = rem / 48, k2 = rem % 48;
        int e0 = (2 * k2) * HID_F + n;
        int e1 = e0 + HID_F;
        const float* m = M1 + (size_t)t * IN_F * HID_F;
        g_B1h[i] = pack_h2(W1[e0] * m[e0], W1[e1] * m[e1]);
    }
    if (i < S2) {
        int t = i / (OUT_F * 64);
        int rem = i % (OUT_F * 64);
        int n = rem / 64, k2 = rem % 64;
        int e0 = (2 * k2) * OUT_F + n;
        int e1 = e0 + OUT_F;
        const float* m = M2 + (size_t)t * HID_F * OUT_F;
        g_B2h[i] = pack_h2(W2[e0] * m[e0], W2[e1] * m[e1]);
    }
}

// ---------------- SpMM2: out[t,n,:] = spmm(p_t) for ALL t, unroll 4 -----------
__device__ __forceinline__ void acc8(float acc[16], int base, uint4 u, float w) {
    const __half2* h = (const __half2*)&u;
    #pragma unroll
    for (int q = 0; q < 4; q++) {
        float2 f = __half22float2(h[q]);
        acc[base + 2 * q]     += w * f.x;
        acc[base + 2 * q + 1] += w * f.y;
    }
}

__global__ void k_spmm_all(float* __restrict__ out) {
    int warp = (blockIdx.x * blockDim.x + threadIdx.x) >> 5;
    int lane = threadIdx.x & 31;
    if (warp >= NN) return;
    int r0 = g_rowptr[warp], r1 = g_rowptr[warp + 1];

    float acc[16];
    #pragma unroll
    for (int i = 0; i < 16; i++) acc[i] = 0.f;

    int r = r0;
    for (; r + 3 < r1; r += 4) {
        int2 e0 = g_epack[r],     e1 = g_epack[r + 1];
        int2 e2 = g_epack[r + 2], e3 = g_epack[r + 3];
        const uint4* p0 = (const uint4*)(g_ph + (size_t)e0.x * 512) + lane * 2;
        const uint4* p1 = (const uint4*)(g_ph + (size_t)e1.x * 512) + lane * 2;
        const uint4* p2 = (const uint4*)(g_ph + (size_t)e2.x * 512) + lane * 2;
        const uint4* p3 = (const uint4*)(g_ph + (size_t)e3.x * 512) + lane * 2;
        uint4 u00 = p0[0], u01 = p0[1];
        uint4 u10 = p1[0], u11 = p1[1];
        uint4 u20 = p2[0], u21 = p2[1];
        uint4 u30 = p3[0], u31 = p3[1];
        float w0 = __int_as_float(e0.y), w1 = __int_as_float(e1.y);
        float w2 = __int_as_float(e2.y), w3 = __int_as_float(e3.y);
        acc8(acc, 0, u00, w0); acc8(acc, 8, u01, w0);
        acc8(acc, 0, u10, w1); acc8(acc, 8, u11, w1);
        acc8(acc, 0, u20, w2); acc8(acc, 8, u21, w2);
        acc8(acc, 0, u30, w3); acc8(acc, 8, u31, w3);
    }
    for (; r < r1; r++) {
        int2 e = g_epack[r];
        float w = __int_as_float(e.y);
        const uint4* p = (const uint4*)(g_ph + (size_t)e.x * 512) + lane * 2;
        uint4 u0 = p[0], u1 = p[1];
        acc8(acc, 0, u0, w); acc8(acc, 8, u1, w);
    }

    int t  = lane >> 2;
    int c0 = (lane & 3) * 16;
    float* op = out + ((size_t)t * NN + warp) * OUT_F + c0;
    #pragma unroll
    for (int q = 0; q < 4; q++)
        *(float4*)(op + q * 4) = make_float4(acc[q * 4], acc[q * 4 + 1],
                                             acc[q * 4 + 2], acc[q * 4 + 3]);
}

// ---------------- fused: in-CTA spmm96 + fp16 mma GEMM chain -------------------
// smem uint32 (fp16x2) layout, padded lds for conflict-free fragment access:
//   A  128 rows x 48 k2, ld 52  @ 0       (6656)
//   B1 128 n    x 48 k2, ld 52  @ 6656    (6656)
//   B2 64  n    x 64 k2, ld 68  @ 13312   (4352)
//   H  128 rows x 64 k2, ld 68  @ 17664   (8704)
#define OFF_A   0
#define LDA     52
#define OFF_B1  6656
#define LDB1    52
#define OFF_B2  13312
#define LDB2    68
#define OFF_H   17664
#define LDH     68
#define FUSED_WORDS (OFF_H + 128 * LDH)            // 26368 words
#define FUSED_SMEM  (FUSED_WORDS * 4)              // 105472 bytes

__global__ void __launch_bounds__(256, 2)
k_fused_gemm() {
    extern __shared__ uint32_t sm[];
    const int tid  = threadIdx.x;
    const int wid  = tid >> 5;
    const int lane = tid & 31;
    const int gid  = lane >> 2;
    const int tig  = lane & 3;
    const int row0 = blockIdx.x * 128;

    // ---- in-CTA SpMM1: warp computes agg1 for its 16 rows, straight to smem A
    {
        const uint32_t* xh = (const uint32_t*)g_xh;   // half2 granules, 48/row
        const bool hi = lane < 16;
        #pragma unroll 1
        for (int i = 0; i < 16; i++) {
            int r = wid * 16 + i;
            int node = row0 + r;
            float2 A0 = make_float2(0.f, 0.f), A1 = make_float2(0.f, 0.f);
            if (node < NN) {
                int e0r = g_rowptr[node], e1r = g_rowptr[node + 1];
                int e = e0r;
                for (; e + 3 < e1r; e += 4) {
                    int2 q0 = g_epack[e],     q1 = g_epack[e + 1];
                    int2 q2 = g_epack[e + 2], q3 = g_epack[e + 3];
                    uint32_t u00 = xh[q0.x * 48 + lane];
                    uint32_t u10 = xh[q1.x * 48 + lane];
                    uint32_t u20 = xh[q2.x * 48 + lane];
                    uint32_t u30 = xh[q3.x * 48 + lane];
                    uint32_t u01 = hi ? xh[q0.x * 48 + 32 + lane] : 0u;
                    uint32_t u11 = hi ? xh[q1.x * 48 + 32 + lane] : 0u;
                    uint32_t u21 = hi ? xh[q2.x * 48 + 32 + lane] : 0u;
                    uint32_t u31 = hi ? xh[q3.x * 48 + 32 + lane] : 0u;
                    float w0 = __int_as_float(q0.y), w1 = __int_as_float(q1.y);
                    float w2 = __int_as_float(q2.y), w3 = __int_as_float(q3.y);
                    float2 f;
                    f = __half22float2(*(__half2*)&u00); A0.x += w0 * f.x; A0.y += w0 * f.y;
                    f = __half22float2(*(__half2*)&u10); A0.x += w1 * f.x; A0.y += w1 * f.y;
                    f = __half22float2(*(__half2*)&u20); A0.x += w2 * f.x; A0.y += w2 * f.y;
                    f = __half22float2(*(__half2*)&u30); A0.x += w3 * f.x; A0.y += w3 * f.y;
                    f = __half22float2(*(__half2*)&u01); A1.x += w0 * f.x; A1.y += w0 * f.y;
                    f = __half22float2(*(__half2*)&u11); A1.x += w1 * f.x; A1.y += w1 * f.y;
                    f = __half22float2(*(__half2*)&u21); A1.x += w2 * f.x; A1.y += w2 * f.y;
                    f = __half22float2(*(__half2*)&u31); A1.x += w3 * f.x; A1.y += w3 * f.y;
                }
                for (; e < e1r; e++) {
                    int2 q = g_epack[e];
                    float w = __int_as_float(q.y);
                    uint32_t u0 = xh[q.x * 48 + lane];
                    uint32_t u1 = hi ? xh[q.x * 48 + 32 + lane] : 0u;
                    float2 f;
                    f = __half22float2(*(__half2*)&u0); A0.x += w * f.x; A0.y += w * f.y;
                    f = __half22float2(*(__half2*)&u1); A1.x += w * f.x; A1.y += w * f.y;
                }
            }
            sm[OFF_A + r * LDA + lane] = pack_h2(A0.x, A0.y);
            if (hi) sm[OFF_A + r * LDA + 32 + lane] = pack_h2(A1.x, A1.y);
        }
    }

    const int r0 = wid * 16;
    const int rowA = row0 + r0 + gid;
    const int rowB = rowA + 8;

    for (int t = 0; t < TT; t++) {
        __syncthreads();
        {
            const uint32_t* b1 = g_B1h + t * HID_F * 48;
            for (int e = tid; e < HID_F * 48; e += 256)
                sm[OFF_B1 + (e / 48) * LDB1 + (e % 48)] = b1[e];
            const uint32_t* b2 = g_B2h + t * OUT_F * 64;
            for (int e = tid; e < OUT_F * 64; e += 256)
                sm[OFF_B2 + (e >> 6) * LDB2 + (e & 63)] = b2[e];
        }
        __syncthreads();

        // ===== GEMM1: H[128,128] = A[128,96] @ B1, 6 k16-steps =====
        float acc1[16][4];
        #pragma unroll
        for (int j = 0; j < 16; j++)
            #pragma unroll
            for (int i = 0; i < 4; i++) acc1[j][i] = 0.f;

        #pragma unroll
        for (int kb = 0; kb < 6; kb++) {
            const int k2b = kb * 8;
            uint32_t a0 = sm[OFF_A + (r0 + gid)     * LDA + k2b + tig];
            uint32_t a1 = sm[OFF_A + (r0 + gid + 8) * LDA + k2b + tig];
            uint32_t a2 = sm[OFF_A + (r0 + gid)     * LDA + k2b + tig + 4];
            uint32_t a3 = sm[OFF_A + (r0 + gid + 8) * LDA + k2b + tig + 4];
            #pragma unroll
            for (int j = 0; j < 16; j++) {
                uint32_t b0 = sm[OFF_B1 + (j * 8 + gid) * LDB1 + k2b + tig];
                uint32_t b1 = sm[OFF_B1 + (j * 8 + gid) * LDB1 + k2b + tig + 4];
                mma_f16(acc1[j], a0, a1, a2, a3, b0, b1);
            }
        }

        // relu + fp16 pack, store H[row][k2] (warp-private rows)
        #pragma unroll
        for (int j = 0; j < 16; j++) {
            float f0 = acc1[j][0], f1 = acc1[j][1], f2 = acc1[j][2], f3 = acc1[j][3];
            uint32_t uA = pack_h2(f0 > 0.f ? f0 : 0.f, f1 > 0.f ? f1 : 0.f);
            uint32_t uB = pack_h2(f2 > 0.f ? f2 : 0.f, f3 > 0.f ? f3 : 0.f);
            sm[OFF_H + (r0 + gid)     * LDH + 4 * j + tig] = uA;
            sm[OFF_H + (r0 + gid + 8) * LDH + 4 * j + tig] = uB;
        }
        __syncwarp();

        // ===== GEMM2: P[128,64] = H[128,128] @ B2, 8 k16-steps =====
        float acc2[8][4];
        #pragma unroll
        for (int j = 0; j < 8; j++)
            #pragma unroll
            for (int i = 0; i < 4; i++) acc2[j][i] = 0.f;

        #pragma unroll
        for (int kb = 0; kb < 8; kb++) {
            const int k2b = kb * 8;
            uint32_t a0 = sm[OFF_H + (r0 + gid)     * LDH + k2b + tig];
            uint32_t a1 = sm[OFF_H + (r0 + gid + 8) * LDH + k2b + tig];
            uint32_t a2 = sm[OFF_H + (r0 + gid)     * LDH + k2b + tig + 4];
            uint32_t a3 = sm[OFF_H + (r0 + gid + 8) * LDH + k2b + tig + 4];
            #pragma unroll
            for (int j = 0; j < 8; j++) {
                uint32_t b0 = sm[OFF_B2 + (j * 8 + gid) * LDB2 + k2b + tig];
                uint32_t b1 = sm[OFF_B2 + (j * 8 + gid) * LDB2 + k2b + tig + 4];
                mma_f16(acc2[j], a0, a1, a2, a3, b0, b1);
            }
        }

        // ---- epilogue: write p tile as fp16 into g_ph[n][t*64+c]
        if (rowA < NN) {
            __half* p = g_ph + (size_t)rowA * 512 + t * 64;
            #pragma unroll
            for (int j = 0; j < 8; j++)
                *(uint32_t*)(p + j * 8 + 2 * tig) = pack_h2(acc2[j][0], acc2[j][1]);
        }
        if (rowB < NN) {
            __half* p = g_ph + (size_t)rowB * 512 + t * 64;
            #pragma unroll
            for (int j = 0; j < 8; j++)
                *(uint32_t*)(p + j * 8 + 2 * tig) = pack_h2(acc2[j][2], acc2[j][3]);
        }
    }
}

// ---------------- launch ------------------------------------------------------
extern "C" void kernel_launch(void* const* d_in, const int* in_sizes, int n_in,
                              void* d_out, int out_size) {
    (void)in_sizes; (void)n_in; (void)out_size;
    const float* x   = (const float*)d_in[0];
    const float* ew  = (const float*)d_in[1];
    const float* W1  = (const float*)d_in[2];
    const float* W2  = (const float*)d_in[3];
    const float* m1  = (const float*)d_in[4];
    const float* m2  = (const float*)d_in[5];
    const int*   src = (const int*)d_in[6];
    const int*   dst = (const int*)d_in[7];
    float* out = (float*)d_out;

    cudaFuncSetAttribute((const void*)k_fused_gemm,
                         cudaFuncAttributeMaxDynamicSharedMemorySize, FUSED_SMEM);

    // 1. CSR build + conversions (EE % 4 == 0)
    k_hist<<<(EE / 4 + 255) / 256, 256>>>((const int4*)dst);
    k_scan1<<<NBLK, SCAN_BLK>>>();
    k_scan23<<<NBLK, SCAN_BLK>>>();
    k_scatter<<<(EE / 4 + 255) / 256, 256>>>((const int4*)src, (const int4*)dst,
                                             (const float4*)ew);
    k_convert<<<(XW + 255) / 256, 256>>>(x, W1, W2, m1, m2);

    // 2+3+4. fused: in-CTA spmm96 + p_t = relu(agg1 @ B1_t) @ B2_t
    k_fused_gemm<<<(NN + 127) / 128, 256, FUSED_SMEM>>>();

    // 5. out = spmm(p) for all 8 samples in one pass
    k_spmm_all<<<(NN * 32 + 255) / 256, 256>>>(out);
}

// round 9
// speedup vs baseline: 1.1893x; 1.1893x over previous
#include <cuda_runtime.h>
#include <cuda_fp16.h>
#include <cstdint>

// Problem constants (fixed by the dataset)
#define NN    50000
#define EE    800000
#define IN_F  96
#define HID_F 128
#define OUT_F 64
#define TT    8

#define SCAN_BLK 512
#define NBLK ((NN + SCAN_BLK - 1) / SCAN_BLK)    // 98

// ---------------- static device scratch (no allocations allowed) -------------
__device__ int      g_counts[NN];      // zero-init at load; re-zeroed by k_scan23
__device__ int      g_rowptr[NN + 1];
__device__ int      g_cursor[NN];
__device__ int      g_bsum[NBLK];
__device__ int2     g_epack[EE];                            // (src, w-as-bits)
__device__ __half   g_xh[(size_t)NN * IN_F];                // 9.6 MB fp16 x
__device__ __half   g_agg1h[(size_t)NN * IN_F];             // 9.6 MB fp16 agg1
__device__ __half   g_ph[(size_t)NN * TT * OUT_F];          // 51.2 MB, [n][t*64+c]
__device__ uint32_t g_B1h[TT * HID_F * 48];                 // fp16x2 [t][n][k2]
__device__ uint32_t g_B2h[TT * OUT_F * 64];                 // fp16x2 [t][n][k2]

// ---------------- helpers ------------------------------------------------------
__device__ __forceinline__ void mma_f16(float d[4],
                                        uint32_t a0, uint32_t a1, uint32_t a2, uint32_t a3,
                                        uint32_t b0, uint32_t b1) {
    asm volatile("mma.sync.aligned.m16n8k16.row.col.f32.f16.f16.f32 "
        "{%0,%1,%2,%3}, {%4,%5,%6,%7}, {%8,%9}, {%0,%1,%2,%3};"
        : "+f"(d[0]), "+f"(d[1]), "+f"(d[2]), "+f"(d[3])
        : "r"(a0), "r"(a1), "r"(a2), "r"(a3), "r"(b0), "r"(b1));
}
__device__ __forceinline__ uint32_t pack_h2(float a, float b) {
    __half2 h = __float22half2_rn(make_float2(a, b));
    return *(uint32_t*)&h;
}

// ---------------- CSR build --------------------------------------------------
__global__ void k_hist(const int* __restrict__ dst) {
    int e = blockIdx.x * blockDim.x + threadIdx.x;
    if (e < EE) atomicAdd(&g_counts[dst[e]], 1);
}
__global__ void k_scan1() {
    __shared__ int s[SCAN_BLK];
    int b = blockIdx.x, tid = threadIdx.x;
    int i = b * SCAN_BLK + tid;
    s[tid] = (i < NN) ? g_counts[i] : 0;
    __syncthreads();
    #pragma unroll
    for (int off = SCAN_BLK / 2; off > 0; off >>= 1) {
        if (tid < off) s[tid] += s[tid + off];
        __syncthreads();
    }
    if (tid == 0) g_bsum[b] = s[0];
}
// combined: per-block redundant scan of the 98 block sums + local scan
__global__ void k_scan23() {
    __shared__ int s[SCAN_BLK];
    __shared__ int bs[128];
    __shared__ int boff;
    int b = blockIdx.x, tid = threadIdx.x;
    int i = b * SCAN_BLK + tid;
    int c = (i < NN) ? g_counts[i] : 0;
    s[tid] = c;
    if (tid < 128) bs[tid] = (tid < NBLK) ? g_bsum[tid] : 0;
    __syncthreads();
    if (tid < 128) {
        #pragma unroll
        for (int off = 1; off < 128; off <<= 1) {
            int u = (tid >= off) ? bs[tid - off] : 0;
            __syncthreads();
            bs[tid] += u;
            __syncthreads();
        }
        if (tid == 0) boff = (b == 0) ? 0 : bs[b - 1];
    } else {
        #pragma unroll
        for (int off = 1; off < 128; off <<= 1) { __syncthreads(); __syncthreads(); }
    }
    __syncthreads();
    #pragma unroll
    for (int off = 1; off < SCAN_BLK; off <<= 1) {
        int u = (tid >= off) ? s[tid - off] : 0;
        __syncthreads();
        s[tid] += u;
        __syncthreads();
    }
    if (i < NN) {
        int excl = s[tid] - c + boff;
        g_rowptr[i] = excl;
        g_cursor[i] = excl;
        g_counts[i] = 0;                      // restore invariant for next call
        if (i == NN - 1) g_rowptr[NN] = excl + c;
    }
}
__global__ void k_scatter(const int* __restrict__ src, const int* __restrict__ dst,
                          const float* __restrict__ ew) {
    int e = blockIdx.x * blockDim.x + threadIdx.x;
    if (e >= EE) return;
    int d = dst[e];
    int pos = atomicAdd(&g_cursor[d], 1);
    g_epack[pos] = make_int2(src[e], __float_as_int(ew[e]));
}

// ---------------- convert: x->fp16 AND masked weights -> fp16x2 ----------------
#define XW (NN * IN_F / 2)                 // 2,400,000 half2
__global__ void k_convert(const float* __restrict__ x,
                          const float* __restrict__ W1, const float* __restrict__ W2,
                          const float* __restrict__ M1, const float* __restrict__ M2) {
    int i = blockIdx.x * blockDim.x + threadIdx.x;
    if (i < XW) {
        float2 v = *(const float2*)(x + i * 2);
        *((__half2*)g_xh + i) = __float22half2_rn(v);
    }
    const int S1 = TT * HID_F * 48;        // 49152
    const int S2 = TT * OUT_F * 64;        // 32768
    if (i < S1) {
        int t = i / (HID_F * 48);
        int rem = i % (HID_F * 48);
        int n = rem / 48, k2 = rem % 48;
        int e0 = (2 * k2) * HID_F + n;
        int e1 = e0 + HID_F;
        const float* m = M1 + (size_t)t * IN_F * HID_F;
        g_B1h[i] = pack_h2(W1[e0] * m[e0], W1[e1] * m[e1]);
    }
    if (i < S2) {
        int t = i / (OUT_F * 64);
        int rem = i % (OUT_F * 64);
        int n = rem / 64, k2 = rem % 64;
        int e0 = (2 * k2) * OUT_F + n;
        int e1 = e0 + OUT_F;
        const float* m = M2 + (size_t)t * HID_F * OUT_F;
        g_B2h[i] = pack_h2(W2[e0] * m[e0], W2[e1] * m[e1]);
    }
}

// ---------------- SpMM1: agg1h = spmm(xh), warp per node, unroll 4 ------------
__global__ void k_spmm96() {
    int warp = (blockIdx.x * blockDim.x + threadIdx.x) >> 5;
    int lane = threadIdx.x & 31;
    if (warp >= NN) return;
    int r0 = g_rowptr[warp], r1 = g_rowptr[warp + 1];
    const uint32_t* xh = (const uint32_t*)g_xh;     // half2 granules, 48/row
    const bool hi = lane < 16;

    float2 A0 = make_float2(0.f, 0.f), A1 = make_float2(0.f, 0.f);
    int r = r0;
    for (; r + 3 < r1; r += 4) {
        int2 e0 = g_epack[r],     e1 = g_epack[r + 1];
        int2 e2 = g_epack[r + 2], e3 = g_epack[r + 3];
        uint32_t u00 = xh[e0.x * 48 + lane];
        uint32_t u10 = xh[e1.x * 48 + lane];
        uint32_t u20 = xh[e2.x * 48 + lane];
        uint32_t u30 = xh[e3.x * 48 + lane];
        uint32_t u01 = hi ? xh[e0.x * 48 + 32 + lane] : 0u;
        uint32_t u11 = hi ? xh[e1.x * 48 + 32 + lane] : 0u;
        uint32_t u21 = hi ? xh[e2.x * 48 + 32 + lane] : 0u;
        uint32_t u31 = hi ? xh[e3.x * 48 + 32 + lane] : 0u;
        float w0 = __int_as_float(e0.y), w1 = __int_as_float(e1.y);
        float w2 = __int_as_float(e2.y), w3 = __int_as_float(e3.y);
        float2 f;
        f = __half22float2(*(__half2*)&u00); A0.x += w0 * f.x; A0.y += w0 * f.y;
        f = __half22float2(*(__half2*)&u10); A0.x += w1 * f.x; A0.y += w1 * f.y;
        f = __half22float2(*(__half2*)&u20); A0.x += w2 * f.x; A0.y += w2 * f.y;
        f = __half22float2(*(__half2*)&u30); A0.x += w3 * f.x; A0.y += w3 * f.y;
        f = __half22float2(*(__half2*)&u01); A1.x += w0 * f.x; A1.y += w0 * f.y;
        f = __half22float2(*(__half2*)&u11); A1.x += w1 * f.x; A1.y += w1 * f.y;
        f = __half22float2(*(__half2*)&u21); A1.x += w2 * f.x; A1.y += w2 * f.y;
        f = __half22float2(*(__half2*)&u31); A1.x += w3 * f.x; A1.y += w3 * f.y;
    }
    for (; r < r1; r++) {
        int2 e = g_epack[r];
        float w = __int_as_float(e.y);
        uint32_t u0 = xh[e.x * 48 + lane];
        uint32_t u1 = hi ? xh[e.x * 48 + 32 + lane] : 0u;
        float2 f;
        f = __half22float2(*(__half2*)&u0); A0.x += w * f.x; A0.y += w * f.y;
        f = __half22float2(*(__half2*)&u1); A1.x += w * f.x; A1.y += w * f.y;
    }
    uint32_t* o = (uint32_t*)g_agg1h + (size_t)warp * 48;
    o[lane] = pack_h2(A0.x, A0.y);
    if (hi) o[32 + lane] = pack_h2(A1.x, A1.y);
}

// ---------------- SpMM2: out[t,n,:] = spmm(p_t) for ALL t, unroll 4 -----------
__device__ __forceinline__ void acc8(float acc[16], int base, uint4 u, float w) {
    const __half2* h = (const __half2*)&u;
    #pragma unroll
    for (int q = 0; q < 4; q++) {
        float2 f = __half22float2(h[q]);
        acc[base + 2 * q]     += w * f.x;
        acc[base + 2 * q + 1] += w * f.y;
    }
}

__global__ void k_spmm_all(float* __restrict__ out) {
    int warp = (blockIdx.x * blockDim.x + threadIdx.x) >> 5;
    int lane = threadIdx.x & 31;
    if (warp >= NN) return;
    int r0 = g_rowptr[warp], r1 = g_rowptr[warp + 1];

    float acc[16];
    #pragma unroll
    for (int i = 0; i < 16; i++) acc[i] = 0.f;

    int r = r0;
    for (; r + 3 < r1; r += 4) {
        int2 e0 = g_epack[r],     e1 = g_epack[r + 1];
        int2 e2 = g_epack[r + 2], e3 = g_epack[r + 3];
        const uint4* p0 = (const uint4*)(g_ph + (size_t)e0.x * 512) + lane * 2;
        const uint4* p1 = (const uint4*)(g_ph + (size_t)e1.x * 512) + lane * 2;
        const uint4* p2 = (const uint4*)(g_ph + (size_t)e2.x * 512) + lane * 2;
        const uint4* p3 = (const uint4*)(g_ph + (size_t)e3.x * 512) + lane * 2;
        uint4 u00 = p0[0], u01 = p0[1];
        uint4 u10 = p1[0], u11 = p1[1];
        uint4 u20 = p2[0], u21 = p2[1];
        uint4 u30 = p3[0], u31 = p3[1];
        float w0 = __int_as_float(e0.y), w1 = __int_as_float(e1.y);
        float w2 = __int_as_float(e2.y), w3 = __int_as_float(e3.y);
        acc8(acc, 0, u00, w0); acc8(acc, 8, u01, w0);
        acc8(acc, 0, u10, w1); acc8(acc, 8, u11, w1);
        acc8(acc, 0, u20, w2); acc8(acc, 8, u21, w2);
        acc8(acc, 0, u30, w3); acc8(acc, 8, u31, w3);
    }
    for (; r < r1; r++) {
        int2 e = g_epack[r];
        float w = __int_as_float(e.y);
        const uint4* p = (const uint4*)(g_ph + (size_t)e.x * 512) + lane * 2;
        uint4 u0 = p[0], u1 = p[1];
        acc8(acc, 0, u0, w); acc8(acc, 8, u1, w);
    }

    int t  = lane >> 2;
    int c0 = (lane & 3) * 16;
    float* op = out + ((size_t)t * NN + warp) * OUT_F + c0;
    #pragma unroll
    for (int q = 0; q < 4; q++)
        *(float4*)(op + q * 4) = make_float4(acc[q * 4], acc[q * 4 + 1],
                                             acc[q * 4 + 2], acc[q * 4 + 3]);
}

// ---------------- fused fp16 mma GEMM (loop over all t per CTA) ---------------
// smem uint32 (fp16x2) layout, padded lds for conflict-free fragment access:
//   A  128 rows x 48 k2, ld 52  @ 0       (6656)
//   B1 128 n    x 48 k2, ld 52  @ 6656    (6656)
//   B2 64  n    x 64 k2, ld 68  @ 13312   (4352)
//   H  128 rows x 64 k2, ld 68  @ 17664   (8704)
#define OFF_A   0
#define LDA     52
#define OFF_B1  6656
#define LDB1    52
#define OFF_B2  13312
#define LDB2    68
#define OFF_H   17664
#define LDH     68
#define FUSED_WORDS (OFF_H + 128 * LDH)            // 26368 words
#define FUSED_SMEM  (FUSED_WORDS * 4)              // 105472 bytes

__global__ void __launch_bounds__(256, 2)
k_fused_gemm() {
    extern __shared__ uint32_t sm[];
    const int tid  = threadIdx.x;
    const int wid  = tid >> 5;
    const int lane = tid & 31;
    const int gid  = lane >> 2;
    const int tig  = lane & 3;
    const int row0 = blockIdx.x * 128;

    // ---- stage A tile ONCE (fp16x2)
    const uint32_t* ah = (const uint32_t*)g_agg1h;
    for (int e = tid; e < 128 * 48; e += 256) {
        int r = e / 48, k2 = e % 48;
        int gr = row0 + r;
        sm[OFF_A + r * LDA + k2] = (gr < NN) ? ah[gr * 48 + k2] : 0u;
    }

    const int r0 = wid * 16;
    const int rowA = row0 + r0 + gid;
    const int rowB = rowA + 8;

    for (int t = 0; t < TT; t++) {
        __syncthreads();
        {
            const uint32_t* b1 = g_B1h + t * HID_F * 48;
            for (int e = tid; e < HID_F * 48; e += 256)
                sm[OFF_B1 + (e / 48) * LDB1 + (e % 48)] = b1[e];
            const uint32_t* b2 = g_B2h + t * OUT_F * 64;
            for (int e = tid; e < OUT_F * 64; e += 256)
                sm[OFF_B2 + (e >> 6) * LDB2 + (e & 63)] = b2[e];
        }
        __syncthreads();

        // ===== GEMM1: H[128,128] = A[128,96] @ B1, 6 k16-steps =====
        float acc1[16][4];
        #pragma unroll
        for (int j = 0; j < 16; j++)
            #pragma unroll
            for (int i = 0; i < 4; i++) acc1[j][i] = 0.f;

        #pragma unroll
        for (int kb = 0; kb < 6; kb++) {
            const int k2b = kb * 8;
            uint32_t a0 = sm[OFF_A + (r0 + gid)     * LDA + k2b + tig];
            uint32_t a1 = sm[OFF_A + (r0 + gid + 8) * LDA + k2b + tig];
            uint32_t a2 = sm[OFF_A + (r0 + gid)     * LDA + k2b + tig + 4];
            uint32_t a3 = sm[OFF_A + (r0 + gid + 8) * LDA + k2b + tig + 4];
            #pragma unroll
            for (int j = 0; j < 16; j++) {
                uint32_t b0 = sm[OFF_B1 + (j * 8 + gid) * LDB1 + k2b + tig];
                uint32_t b1 = sm[OFF_B1 + (j * 8 + gid) * LDB1 + k2b + tig + 4];
                mma_f16(acc1[j], a0, a1, a2, a3, b0, b1);
            }
        }

        // relu + fp16 pack, store H[row][k2] (warp-private rows)
        #pragma unroll
        for (int j = 0; j < 16; j++) {
            float f0 = acc1[j][0], f1 = acc1[j][1], f2 = acc1[j][2], f3 = acc1[j][3];
            uint32_t uA = pack_h2(f0 > 0.f ? f0 : 0.f, f1 > 0.f ? f1 : 0.f);
            uint32_t uB = pack_h2(f2 > 0.f ? f2 : 0.f, f3 > 0.f ? f3 : 0.f);
            sm[OFF_H + (r0 + gid)     * LDH + 4 * j + tig] = uA;
            sm[OFF_H + (r0 + gid + 8) * LDH + 4 * j + tig] = uB;
        }
        __syncwarp();

        // ===== GEMM2: P[128,64] = H[128,128] @ B2, 8 k16-steps =====
        float acc2[8][4];
        #pragma unroll
        for (int j = 0; j < 8; j++)
            #pragma unroll
            for (int i = 0; i < 4; i++) acc2[j][i] = 0.f;

        #pragma unroll
        for (int kb = 0; kb < 8; kb++) {
            const int k2b = kb * 8;
            uint32_t a0 = sm[OFF_H + (r0 + gid)     * LDH + k2b + tig];
            uint32_t a1 = sm[OFF_H + (r0 + gid + 8) * LDH + k2b + tig];
            uint32_t a2 = sm[OFF_H + (r0 + gid)     * LDH + k2b + tig + 4];
            uint32_t a3 = sm[OFF_H + (r0 + gid + 8) * LDH + k2b + tig + 4];
            #pragma unroll
            for (int j = 0; j < 8; j++) {
                uint32_t b0 = sm[OFF_B2 + (j * 8 + gid) * LDB2 + k2b + tig];
                uint32_t b1 = sm[OFF_B2 + (j * 8 + gid) * LDB2 + k2b + tig + 4];
                mma_f16(acc2[j], a0, a1, a2, a3, b0, b1);
            }
        }

        // ---- epilogue: write p tile as fp16 into g_ph[n][t*64+c]
        if (rowA < NN) {
            __half* p = g_ph + (size_t)rowA * 512 + t * 64;
            #pragma unroll
            for (int j = 0; j < 8; j++)
                *(uint32_t*)(p + j * 8 + 2 * tig) = pack_h2(acc2[j][0], acc2[j][1]);
        }
        if (rowB < NN) {
            __half* p = g_ph + (size_t)rowB * 512 + t * 64;
            #pragma unroll
            for (int j = 0; j < 8; j++)
                *(uint32_t*)(p + j * 8 + 2 * tig) = pack_h2(acc2[j][2], acc2[j][3]);
        }
    }
}

// ---------------- launch ------------------------------------------------------
extern "C" void kernel_launch(void* const* d_in, const int* in_sizes, int n_in,
                              void* d_out, int out_size) {
    (void)in_sizes; (void)n_in; (void)out_size;
    const float* x   = (const float*)d_in[0];
    const float* ew  = (const float*)d_in[1];
    const float* W1  = (const float*)d_in[2];
    const float* W2  = (const float*)d_in[3];
    const float* m1  = (const float*)d_in[4];
    const float* m2  = (const float*)d_in[5];
    const int*   src = (const int*)d_in[6];
    const int*   dst = (const int*)d_in[7];
    float* out = (float*)d_out;

    cudaFuncSetAttribute((const void*)k_fused_gemm,
                         cudaFuncAttributeMaxDynamicSharedMemorySize, FUSED_SMEM);

    // 1. CSR build + conversions (scalar hist/scatter — measured faster than int4)
    k_hist<<<(EE + 255) / 256, 256>>>(dst);
    k_scan1<<<NBLK, SCAN_BLK>>>();
    k_scan23<<<NBLK, SCAN_BLK>>>();
    k_scatter<<<(EE + 255) / 256, 256>>>(src, dst, ew);
    k_convert<<<(XW + 255) / 256, 256>>>(x, W1, W2, m1, m2);

    // 2. agg1h = spmm(xh)
    k_spmm96<<<(NN * 32 + 255) / 256, 256>>>();

    // 3+4. fused fp16 mma: p_t = relu(agg1 @ B1_t) @ B2_t
    k_fused_gemm<<<(NN + 127) / 128, 256, FUSED_SMEM>>>();

    // 5. out = spmm(p) for all 8 samples in one pass
    k_spmm_all<<<(NN * 32 + 255) / 256, 256>>>(out);
}

// round 10
// speedup vs baseline: 1.2046x; 1.0128x over previous
#include <cuda_runtime.h>
#include <cuda_fp16.h>
#include <cstdint>

// Problem constants (fixed by the dataset)
#define NN    50000
#define EE    800000
#define IN_F  96
#define HID_F 128
#define OUT_F 64
#define TT    8

#define SCAN_BLK 512
#define NBLK ((NN + SCAN_BLK - 1) / SCAN_BLK)    // 98

// ---------------- static device scratch (no allocations allowed) -------------
__device__ int      g_counts[NN];      // zero-init at load; re-zeroed by k_scan
__device__ int      g_rowptr[NN + 1];
__device__ int      g_cursor[NN];
__device__ int      g_bsum[NBLK];      // sentinel -1 written by k_convert each call
__device__ int2     g_epack[EE];                            // (src, w-as-bits)
__device__ __half   g_xh[(size_t)NN * IN_F];                // 9.6 MB fp16 x
__device__ __half   g_agg1h[(size_t)NN * IN_F];             // 9.6 MB fp16 agg1
__device__ __half   g_ph[(size_t)NN * TT * OUT_F];          // 51.2 MB, [n][t*64+c]
__device__ uint32_t g_B1h[TT * HID_F * 48];                 // fp16x2 [t][n][k2]
__device__ uint32_t g_B2h[TT * OUT_F * 64];                 // fp16x2 [t][n][k2]

// ---------------- helpers ------------------------------------------------------
__device__ __forceinline__ void mma_f16(float d[4],
                                        uint32_t a0, uint32_t a1, uint32_t a2, uint32_t a3,
                                        uint32_t b0, uint32_t b1) {
    asm volatile("mma.sync.aligned.m16n8k16.row.col.f32.f16.f16.f32 "
        "{%0,%1,%2,%3}, {%4,%5,%6,%7}, {%8,%9}, {%0,%1,%2,%3};"
        : "+f"(d[0]), "+f"(d[1]), "+f"(d[2]), "+f"(d[3])
        : "r"(a0), "r"(a1), "r"(a2), "r"(a3), "r"(b0), "r"(b1));
}
__device__ __forceinline__ uint32_t pack_h2(float a, float b) {
    __half2 h = __float22half2_rn(make_float2(a, b));
    return *(uint32_t*)&h;
}

// ---------------- convert + hist + sentinel (fused front-end) ------------------
#define XW (NN * IN_F / 2)                 // 2,400,000 half2
__global__ void k_convert(const float* __restrict__ x,
                          const float* __restrict__ W1, const float* __restrict__ W2,
                          const float* __restrict__ M1, const float* __restrict__ M2,
                          const int* __restrict__ dst) {
    int i = blockIdx.x * blockDim.x + threadIdx.x;
    if (i < NBLK) g_bsum[i] = -1;                       // sentinel for k_scan
    if (i < EE) atomicAdd(&g_counts[dst[i]], 1);        // degree histogram
    if (i < XW) {
        float2 v = *(const float2*)(x + i * 2);
        *((__half2*)g_xh + i) = __float22half2_rn(v);
    }
    const int S1 = TT * HID_F * 48;        // 49152
    const int S2 = TT * OUT_F * 64;        // 32768
    if (i < S1) {
        int t = i / (HID_F * 48);
        int rem = i % (HID_F * 48);
        int n = rem / 48, k2 = rem % 48;
        int e0 = (2 * k2) * HID_F + n;
        int e1 = e0 + HID_F;
        const float* m = M1 + (size_t)t * IN_F * HID_F;
        g_B1h[i] = pack_h2(W1[e0] * m[e0], W1[e1] * m[e1]);
    }
    if (i < S2) {
        int t = i / (OUT_F * 64);
        int rem = i % (OUT_F * 64);
        int n = rem / 64, k2 = rem % 64;
        int e0 = (2 * k2) * OUT_F + n;
        int e1 = e0 + OUT_F;
        const float* m = M2 + (size_t)t * HID_F * OUT_F;
        g_B2h[i] = pack_h2(W2[e0] * m[e0], W2[e1] * m[e1]);
    }
}

// ---------------- single-kernel scan (aggregate exchange via sentinel) ---------
// All NBLK=98 blocks are co-resident (one wave), so each block publishes its
// aggregate and polls predecessors. g_bsum pre-set to -1 by k_convert.
__global__ void k_scan() {
    __shared__ int s[SCAN_BLK];
    __shared__ int bs[128];
    int b = blockIdx.x, tid = threadIdx.x;
    int i = b * SCAN_BLK + tid;
    int c = (i < NN) ? g_counts[i] : 0;
    s[tid] = c;
    __syncthreads();
    // local inclusive scan
    #pragma unroll
    for (int off = 1; off < SCAN_BLK; off <<= 1) {
        int u = (tid >= off) ? s[tid - off] : 0;
        __syncthreads();
        s[tid] += u;
        __syncthreads();
    }
    // publish this block's aggregate (atomics give cross-block visibility)
    if (tid == 0) atomicExch(&g_bsum[b], s[SCAN_BLK - 1]);
    // collect predecessor aggregates (parallel poll, counts are >= 0 != -1)
    if (tid < 128) {
        int v = 0;
        if (tid < b) {
            int a;
            do { a = atomicAdd(&g_bsum[tid], 0); } while (a == -1);
            v = a;
        }
        bs[tid] = v;
    }
    __syncthreads();
    #pragma unroll
    for (int off = 64; off > 0; off >>= 1) {
        if (tid < off) bs[tid] += bs[tid + off];
        __syncthreads();
    }
    int boff = bs[0];
    if (i < NN) {
        int excl = s[tid] - c + boff;
        g_rowptr[i] = excl;
        g_cursor[i] = excl;
        g_counts[i] = 0;                      // restore invariant for next call
        if (i == NN - 1) g_rowptr[NN] = excl + c;
    }
}

__global__ void k_scatter(const int* __restrict__ src, const int* __restrict__ dst,
                          const float* __restrict__ ew) {
    int e = blockIdx.x * blockDim.x + threadIdx.x;
    if (e >= EE) return;
    int d = dst[e];
    int pos = atomicAdd(&g_cursor[d], 1);
    g_epack[pos] = make_int2(src[e], __float_as_int(ew[e]));
}

// ---------------- SpMM1: agg1h = spmm(xh), warp per node, LDG.64 x 24 lanes ----
__global__ void k_spmm96() {
    int warp = (blockIdx.x * blockDim.x + threadIdx.x) >> 5;
    int lane = threadIdx.x & 31;
    if (warp >= NN) return;
    int r0 = g_rowptr[warp], r1 = g_rowptr[warp + 1];
    const uint2* xh = (const uint2*)g_xh;     // 24 uint2 (8B) per 192B row
    const bool act = lane < 24;

    // lane owns channels [4*lane, 4*lane+4): two half2 pairs
    float2 A0 = make_float2(0.f, 0.f), A1 = make_float2(0.f, 0.f);
    uint2 z = make_uint2(0u, 0u);
    int r = r0;
    for (; r + 3 < r1; r += 4) {
        int2 e0 = g_epack[r],     e1 = g_epack[r + 1];
        int2 e2 = g_epack[r + 2], e3 = g_epack[r + 3];
        uint2 u0 = act ? xh[e0.x * 24 + lane] : z;
        uint2 u1 = act ? xh[e1.x * 24 + lane] : z;
        uint2 u2 = act ? xh[e2.x * 24 + lane] : z;
        uint2 u3 = act ? xh[e3.x * 24 + lane] : z;
        float w0 = __int_as_float(e0.y), w1 = __int_as_float(e1.y);
        float w2 = __int_as_float(e2.y), w3 = __int_as_float(e3.y);
        float2 f;
        f = __half22float2(*(__half2*)&u0.x); A0.x += w0 * f.x; A0.y += w0 * f.y;
        f = __half22float2(*(__half2*)&u0.y); A1.x += w0 * f.x; A1.y += w0 * f.y;
        f = __half22float2(*(__half2*)&u1.x); A0.x += w1 * f.x; A0.y += w1 * f.y;
        f = __half22float2(*(__half2*)&u1.y); A1.x += w1 * f.x; A1.y += w1 * f.y;
        f = __half22float2(*(__half2*)&u2.x); A0.x += w2 * f.x; A0.y += w2 * f.y;
        f = __half22float2(*(__half2*)&u2.y); A1.x += w2 * f.x; A1.y += w2 * f.y;
        f = __half22float2(*(__half2*)&u3.x); A0.x += w3 * f.x; A0.y += w3 * f.y;
        f = __half22float2(*(__half2*)&u3.y); A1.x += w3 * f.x; A1.y += w3 * f.y;
    }
    for (; r < r1; r++) {
        int2 e = g_epack[r];
        float w = __int_as_float(e.y);
        uint2 u = act ? xh[e.x * 24 + lane] : z;
        float2 f;
        f = __half22float2(*(__half2*)&u.x); A0.x += w * f.x; A0.y += w * f.y;
        f = __half22float2(*(__half2*)&u.y); A1.x += w * f.x; A1.y += w * f.y;
    }
    if (act) {
        uint2 o = make_uint2(pack_h2(A0.x, A0.y), pack_h2(A1.x, A1.y));
        ((uint2*)g_agg1h)[(size_t)warp * 24 + lane] = o;
    }
}

// ---------------- SpMM2: out[t,n,:] = spmm(p_t) for ALL t, unroll 4 -----------
__device__ __forceinline__ void acc8(float acc[16], int base, uint4 u, float w) {
    const __half2* h = (const __half2*)&u;
    #pragma unroll
    for (int q = 0; q < 4; q++) {
        float2 f = __half22float2(h[q]);
        acc[base + 2 * q]     += w * f.x;
        acc[base + 2 * q + 1] += w * f.y;
    }
}

__global__ void k_spmm_all(float* __restrict__ out) {
    int warp = (blockIdx.x * blockDim.x + threadIdx.x) >> 5;
    int lane = threadIdx.x & 31;
    if (warp >= NN) return;
    int r0 = g_rowptr[warp], r1 = g_rowptr[warp + 1];

    float acc[16];
    #pragma unroll
    for (int i = 0; i < 16; i++) acc[i] = 0.f;

    int r = r0;
    for (; r + 3 < r1; r += 4) {
        int2 e0 = g_epack[r],     e1 = g_epack[r + 1];
        int2 e2 = g_epack[r + 2], e3 = g_epack[r + 3];
        const uint4* p0 = (const uint4*)(g_ph + (size_t)e0.x * 512) + lane * 2;
        const uint4* p1 = (const uint4*)(g_ph + (size_t)e1.x * 512) + lane * 2;
        const uint4* p2 = (const uint4*)(g_ph + (size_t)e2.x * 512) + lane * 2;
        const uint4* p3 = (const uint4*)(g_ph + (size_t)e3.x * 512) + lane * 2;
        uint4 u00 = p0[0], u01 = p0[1];
        uint4 u10 = p1[0], u11 = p1[1];
        uint4 u20 = p2[0], u21 = p2[1];
        uint4 u30 = p3[0], u31 = p3[1];
        float w0 = __int_as_float(e0.y), w1 = __int_as_float(e1.y);
        float w2 = __int_as_float(e2.y), w3 = __int_as_float(e3.y);
        acc8(acc, 0, u00, w0); acc8(acc, 8, u01, w0);
        acc8(acc, 0, u10, w1); acc8(acc, 8, u11, w1);
        acc8(acc, 0, u20, w2); acc8(acc, 8, u21, w2);
        acc8(acc, 0, u30, w3); acc8(acc, 8, u31, w3);
    }
    for (; r < r1; r++) {
        int2 e = g_epack[r];
        float w = __int_as_float(e.y);
        const uint4* p = (const uint4*)(g_ph + (size_t)e.x * 512) + lane * 2;
        uint4 u0 = p[0], u1 = p[1];
        acc8(acc, 0, u0, w); acc8(acc, 8, u1, w);
    }

    int t  = lane >> 2;
    int c0 = (lane & 3) * 16;
    float* op = out + ((size_t)t * NN + warp) * OUT_F + c0;
    #pragma unroll
    for (int q = 0; q < 4; q++)
        *(float4*)(op + q * 4) = make_float4(acc[q * 4], acc[q * 4 + 1],
                                             acc[q * 4 + 2], acc[q * 4 + 3]);
}

// ---------------- fused fp16 mma GEMM (loop over all t per CTA) ---------------
// smem uint32 (fp16x2) layout, padded lds for conflict-free fragment access:
//   A  128 rows x 48 k2, ld 52  @ 0       (6656)
//   B1 128 n    x 48 k2, ld 52  @ 6656    (6656)
//   B2 64  n    x 64 k2, ld 68  @ 13312   (4352)
//   H  128 rows x 64 k2, ld 68  @ 17664   (8704)
#define OFF_A   0
#define LDA     52
#define OFF_B1  6656
#define LDB1    52
#define OFF_B2  13312
#define LDB2    68
#define OFF_H   17664
#define LDH     68
#define FUSED_WORDS (OFF_H + 128 * LDH)            // 26368 words
#define FUSED_SMEM  (FUSED_WORDS * 4)              // 105472 bytes

__global__ void __launch_bounds__(256, 2)
k_fused_gemm() {
    extern __shared__ uint32_t sm[];
    const int tid  = threadIdx.x;
    const int wid  = tid >> 5;
    const int lane = tid & 31;
    const int gid  = lane >> 2;
    const int tig  = lane & 3;
    const int row0 = blockIdx.x * 128;

    // ---- stage A tile ONCE (fp16x2)
    const uint32_t* ah = (const uint32_t*)g_agg1h;
    for (int e = tid; e < 128 * 48; e += 256) {
        int r = e / 48, k2 = e % 48;
        int gr = row0 + r;
        sm[OFF_A + r * LDA + k2] = (gr < NN) ? ah[gr * 48 + k2] : 0u;
    }

    const int r0 = wid * 16;
    const int rowA = row0 + r0 + gid;
    const int rowB = rowA + 8;

    for (int t = 0; t < TT; t++) {
        __syncthreads();
        {
            const uint32_t* b1 = g_B1h + t * HID_F * 48;
            for (int e = tid; e < HID_F * 48; e += 256)
                sm[OFF_B1 + (e / 48) * LDB1 + (e % 48)] = b1[e];
            const uint32_t* b2 = g_B2h + t * OUT_F * 64;
            for (int e = tid; e < OUT_F * 64; e += 256)
                sm[OFF_B2 + (e >> 6) * LDB2 + (e & 63)] = b2[e];
        }
        __syncthreads();

        // ===== GEMM1: H[128,128] = A[128,96] @ B1, 6 k16-steps =====
        float acc1[16][4];
        #pragma unroll
        for (int j = 0; j < 16; j++)
            #pragma unroll
            for (int i = 0; i < 4; i++) acc1[j][i] = 0.f;

        #pragma unroll
        for (int kb = 0; kb < 6; kb++) {
            const int k2b = kb * 8;
            uint32_t a0 = sm[OFF_A + (r0 + gid)     * LDA + k2b + tig];
            uint32_t a1 = sm[OFF_A + (r0 + gid + 8) * LDA + k2b + tig];
            uint32_t a2 = sm[OFF_A + (r0 + gid)     * LDA + k2b + tig + 4];
            uint32_t a3 = sm[OFF_A + (r0 + gid + 8) * LDA + k2b + tig + 4];
            #pragma unroll
            for (int j = 0; j < 16; j++) {
                uint32_t b0 = sm[OFF_B1 + (j * 8 + gid) * LDB1 + k2b + tig];
                uint32_t b1 = sm[OFF_B1 + (j * 8 + gid) * LDB1 + k2b + tig + 4];
                mma_f16(acc1[j], a0, a1, a2, a3, b0, b1);
            }
        }

        // relu + fp16 pack, store H[row][k2] (warp-private rows)
        #pragma unroll
        for (int j = 0; j < 16; j++) {
            float f0 = acc1[j][0], f1 = acc1[j][1], f2 = acc1[j][2], f3 = acc1[j][3];
            uint32_t uA = pack_h2(f0 > 0.f ? f0 : 0.f, f1 > 0.f ? f1 : 0.f);
            uint32_t uB = pack_h2(f2 > 0.f ? f2 : 0.f, f3 > 0.f ? f3 : 0.f);
            sm[OFF_H + (r0 + gid)     * LDH + 4 * j + tig] = uA;
            sm[OFF_H + (r0 + gid + 8) * LDH + 4 * j + tig] = uB;
        }
        __syncwarp();

        // ===== GEMM2: P[128,64] = H[128,128] @ B2, 8 k16-steps =====
        float acc2[8][4];
        #pragma unroll
        for (int j = 0; j < 8; j++)
            #pragma unroll
            for (int i = 0; i < 4; i++) acc2[j][i] = 0.f;

        #pragma unroll
        for (int kb = 0; kb < 8; kb++) {
            const int k2b = kb * 8;
            uint32_t a0 = sm[OFF_H + (r0 + gid)     * LDH + k2b + tig];
            uint32_t a1 = sm[OFF_H + (r0 + gid + 8) * LDH + k2b + tig];
            uint32_t a2 = sm[OFF_H + (r0 + gid)     * LDH + k2b + tig + 4];
            uint32_t a3 = sm[OFF_H + (r0 + gid + 8) * LDH + k2b + tig + 4];
            #pragma unroll
            for (int j = 0; j < 8; j++) {
                uint32_t b0 = sm[OFF_B2 + (j * 8 + gid) * LDB2 + k2b + tig];
                uint32_t b1 = sm[OFF_B2 + (j * 8 + gid) * LDB2 + k2b + tig + 4];
                mma_f16(acc2[j], a0, a1, a2, a3, b0, b1);
            }
        }

        // ---- epilogue: write p tile as fp16 into g_ph[n][t*64+c]
        if (rowA < NN) {
            __half* p = g_ph + (size_t)rowA * 512 + t * 64;
            #pragma unroll
            for (int j = 0; j < 8; j++)
                *(uint32_t*)(p + j * 8 + 2 * tig) = pack_h2(acc2[j][0], acc2[j][1]);
        }
        if (rowB < NN) {
            __half* p = g_ph + (size_t)rowB * 512 + t * 64;
            #pragma unroll
            for (int j = 0; j < 8; j++)
                *(uint32_t*)(p + j * 8 + 2 * tig) = pack_h2(acc2[j][2], acc2[j][3]);
        }
    }
}

// ---------------- launch ------------------------------------------------------
extern "C" void kernel_launch(void* const* d_in, const int* in_sizes, int n_in,
                              void* d_out, int out_size) {
    (void)in_sizes; (void)n_in; (void)out_size;
    const float* x   = (const float*)d_in[0];
    const float* ew  = (const float*)d_in[1];
    const float* W1  = (const float*)d_in[2];
    const float* W2  = (const float*)d_in[3];
    const float* m1  = (const float*)d_in[4];
    const float* m2  = (const float*)d_in[5];
    const int*   src = (const int*)d_in[6];
    const int*   dst = (const int*)d_in[7];
    float* out = (float*)d_out;

    cudaFuncSetAttribute((const void*)k_fused_gemm,
                         cudaFuncAttributeMaxDynamicSharedMemorySize, FUSED_SMEM);

    // 1. fused front-end: x->fp16, W.*M->fp16, degree hist, scan sentinel
    k_convert<<<(XW + 255) / 256, 256>>>(x, W1, W2, m1, m2, dst);
    // 2. single-kernel scan -> rowptr/cursor (+ counts re-zeroed)
    k_scan<<<NBLK, SCAN_BLK>>>();
    // 3. CSR scatter (scalar — measured faster than vectorized)
    k_scatter<<<(EE + 255) / 256, 256>>>(src, dst, ew);
    // 4. agg1h = spmm(xh)
    k_spmm96<<<(NN * 32 + 255) / 256, 256>>>();
    // 5. fused fp16 mma: p_t = relu(agg1 @ B1_t) @ B2_t
    k_fused_gemm<<<(NN + 127) / 128, 256, FUSED_SMEM>>>();
    // 6. out = spmm(p) for all 8 samples in one pass
    k_spmm_all<<<(NN * 32 + 255) / 256, 256>>>(out);
}

// round 11
// speedup vs baseline: 1.2156x; 1.0091x over previous
#include <cuda_runtime.h>
#include <cuda_fp16.h>
#include <cstdint>

// Problem constants (fixed by the dataset)
#define NN    50000
#define EE    800000
#define IN_F  96
#define HID_F 128
#define OUT_F 64
#define TT    8

#define SCAN_BLK 512
#define NBLK ((NN + SCAN_BLK - 1) / SCAN_BLK)    // 98

// ---------------- static device scratch (no allocations allowed) -------------
__device__ int      g_counts[NN];      // zero-init at load; re-zeroed by k_scan
__device__ int      g_rowptr[NN + 1];
__device__ int      g_cursor[NN];
__device__ int      g_bsum[NBLK];      // sentinel -1 written by k_convert each call
__device__ int2     g_epack[EE];                            // (src, w-as-bits)
__device__ __half   g_xh[(size_t)NN * IN_F];                // 9.6 MB fp16 x
__device__ __half   g_agg1h[(size_t)NN * IN_F];             // 9.6 MB fp16 agg1
__device__ __half   g_ph[(size_t)NN * TT * OUT_F];          // 51.2 MB, [n][t*64+c]
__device__ uint32_t g_B1h[TT * HID_F * 48];                 // fp16x2 [t][n][k2]
__device__ uint32_t g_B2h[TT * OUT_F * 64];                 // fp16x2 [t][n][k2]

// ---------------- helpers ------------------------------------------------------
__device__ __forceinline__ void mma_f16(float d[4],
                                        uint32_t a0, uint32_t a1, uint32_t a2, uint32_t a3,
                                        uint32_t b0, uint32_t b1) {
    asm volatile("mma.sync.aligned.m16n8k16.row.col.f32.f16.f16.f32 "
        "{%0,%1,%2,%3}, {%4,%5,%6,%7}, {%8,%9}, {%0,%1,%2,%3};"
        : "+f"(d[0]), "+f"(d[1]), "+f"(d[2]), "+f"(d[3])
        : "r"(a0), "r"(a1), "r"(a2), "r"(a3), "r"(b0), "r"(b1));
}
__device__ __forceinline__ uint32_t pack_h2(float a, float b) {
    __half2 h = __float22half2_rn(make_float2(a, b));
    return *(uint32_t*)&h;
}

// ---------------- convert + hist + sentinel (fused front-end) ------------------
#define XW (NN * IN_F / 2)                 // 2,400,000 half2
__global__ void k_convert(const float* __restrict__ x,
                          const int* __restrict__ dst) {
    int i = blockIdx.x * blockDim.x + threadIdx.x;
    if (i < NBLK) g_bsum[i] = -1;                       // sentinel for k_scan
    if (i < EE) atomicAdd(&g_counts[dst[i]], 1);        // degree histogram
    if (i < XW) {
        float2 v = *(const float2*)(x + i * 2);
        *((__half2*)g_xh + i) = __float22half2_rn(v);
    }
}

// ---------------- single-kernel scan (aggregate exchange via sentinel) ---------
__global__ void k_scan() {
    __shared__ int s[SCAN_BLK];
    __shared__ int bs[128];
    int b = blockIdx.x, tid = threadIdx.x;
    int i = b * SCAN_BLK + tid;
    int c = (i < NN) ? g_counts[i] : 0;
    s[tid] = c;
    __syncthreads();
    #pragma unroll
    for (int off = 1; off < SCAN_BLK; off <<= 1) {
        int u = (tid >= off) ? s[tid - off] : 0;
        __syncthreads();
        s[tid] += u;
        __syncthreads();
    }
    if (tid == 0) atomicExch(&g_bsum[b], s[SCAN_BLK - 1]);
    if (tid < 128) {
        int v = 0;
        if (tid < b) {
            int a;
            do { a = atomicAdd(&g_bsum[tid], 0); } while (a == -1);
            v = a;
        }
        bs[tid] = v;
    }
    __syncthreads();
    #pragma unroll
    for (int off = 64; off > 0; off >>= 1) {
        if (tid < off) bs[tid] += bs[tid + off];
        __syncthreads();
    }
    int boff = bs[0];
    if (i < NN) {
        int excl = s[tid] - c + boff;
        g_rowptr[i] = excl;
        g_cursor[i] = excl;
        g_counts[i] = 0;                      // restore invariant for next call
        if (i == NN - 1) g_rowptr[NN] = excl + c;
    }
}

// ---------------- scatter + weight prep (absorbs W.*M conversion) --------------
__global__ void k_scatter(const int* __restrict__ src, const int* __restrict__ dst,
                          const float* __restrict__ ew,
                          const float* __restrict__ W1, const float* __restrict__ W2,
                          const float* __restrict__ M1, const float* __restrict__ M2) {
    int e = blockIdx.x * blockDim.x + threadIdx.x;
    if (e < EE) {
        int d = dst[e];
        int pos = atomicAdd(&g_cursor[d], 1);
        g_epack[pos] = make_int2(src[e], __float_as_int(ew[e]));
    }
    const int S1 = TT * HID_F * 48;        // 49152
    const int S2 = TT * OUT_F * 64;        // 32768
    if (e < S1) {
        int t = e / (HID_F * 48);
        int rem = e % (HID_F * 48);
        int n = rem / 48, k2 = rem % 48;
        int i0 = (2 * k2) * HID_F + n;
        int i1 = i0 + HID_F;
        const float* m = M1 + (size_t)t * IN_F * HID_F;
        g_B1h[e] = pack_h2(W1[i0] * m[i0], W1[i1] * m[i1]);
    }
    if (e < S2) {
        int t = e / (OUT_F * 64);
        int rem = e % (OUT_F * 64);
        int n = rem / 64, k2 = rem % 64;
        int i0 = (2 * k2) * OUT_F + n;
        int i1 = i0 + OUT_F;
        const float* m = M2 + (size_t)t * HID_F * OUT_F;
        g_B2h[e] = pack_h2(W2[i0] * m[i0], W2[i1] * m[i1]);
    }
}

// ---------------- SpMM1: agg1h = spmm(xh), warp per node, LDG.64 x 24 lanes ----
__global__ void k_spmm96() {
    int warp = (blockIdx.x * blockDim.x + threadIdx.x) >> 5;
    int lane = threadIdx.x & 31;
    if (warp >= NN) return;
    int r0 = g_rowptr[warp], r1 = g_rowptr[warp + 1];
    const uint2* xh = (const uint2*)g_xh;     // 24 uint2 (8B) per 192B row
    const bool act = lane < 24;

    float2 A0 = make_float2(0.f, 0.f), A1 = make_float2(0.f, 0.f);
    uint2 z = make_uint2(0u, 0u);
    int r = r0;
    for (; r + 3 < r1; r += 4) {
        int2 e0 = g_epack[r],     e1 = g_epack[r + 1];
        int2 e2 = g_epack[r + 2], e3 = g_epack[r + 3];
        uint2 u0 = act ? xh[e0.x * 24 + lane] : z;
        uint2 u1 = act ? xh[e1.x * 24 + lane] : z;
        uint2 u2 = act ? xh[e2.x * 24 + lane] : z;
        uint2 u3 = act ? xh[e3.x * 24 + lane] : z;
        float w0 = __int_as_float(e0.y), w1 = __int_as_float(e1.y);
        float w2 = __int_as_float(e2.y), w3 = __int_as_float(e3.y);
        float2 f;
        f = __half22float2(*(__half2*)&u0.x); A0.x += w0 * f.x; A0.y += w0 * f.y;
        f = __half22float2(*(__half2*)&u0.y); A1.x += w0 * f.x; A1.y += w0 * f.y;
        f = __half22float2(*(__half2*)&u1.x); A0.x += w1 * f.x; A0.y += w1 * f.y;
        f = __half22float2(*(__half2*)&u1.y); A1.x += w1 * f.x; A1.y += w1 * f.y;
        f = __half22float2(*(__half2*)&u2.x); A0.x += w2 * f.x; A0.y += w2 * f.y;
        f = __half22float2(*(__half2*)&u2.y); A1.x += w2 * f.x; A1.y += w2 * f.y;
        f = __half22float2(*(__half2*)&u3.x); A0.x += w3 * f.x; A0.y += w3 * f.y;
        f = __half22float2(*(__half2*)&u3.y); A1.x += w3 * f.x; A1.y += w3 * f.y;
    }
    for (; r < r1; r++) {
        int2 e = g_epack[r];
        float w = __int_as_float(e.y);
        uint2 u = act ? xh[e.x * 24 + lane] : z;
        float2 f;
        f = __half22float2(*(__half2*)&u.x); A0.x += w * f.x; A0.y += w * f.y;
        f = __half22float2(*(__half2*)&u.y); A1.x += w * f.x; A1.y += w * f.y;
    }
    if (act) {
        uint2 o = make_uint2(pack_h2(A0.x, A0.y), pack_h2(A1.x, A1.y));
        ((uint2*)g_agg1h)[(size_t)warp * 24 + lane] = o;
    }
}

// ---------------- SpMM2: out[t,n,:] = spmm(p_t), 2 warps per node --------------
// Each warp handles one (node, half) pair: 256 of the 512 channels.
// Per edge: ONE coalesced uint4 per lane (512B/warp). Same per-channel fp32
// accumulation order as before -> bit-identical output.
__device__ __forceinline__ void acc8u(float acc[8], uint4 u, float w) {
    const __half2* h = (const __half2*)&u;
    #pragma unroll
    for (int q = 0; q < 4; q++) {
        float2 f = __half22float2(h[q]);
        acc[2 * q]     += w * f.x;
        acc[2 * q + 1] += w * f.y;
    }
}

__global__ void k_spmm_all(float* __restrict__ out) {
    int gw   = (blockIdx.x * blockDim.x + threadIdx.x) >> 5;  // global warp
    int node = gw >> 1;
    int h    = gw & 1;                                         // channel half
    int lane = threadIdx.x & 31;
    if (node >= NN) return;
    int r0 = g_rowptr[node], r1 = g_rowptr[node + 1];

    // row = 64 uint4; this warp covers uint4 [h*32+lane] = halves [h*256+lane*8, +8)
    const uint4* base = (const uint4*)g_ph;
    const int off = h * 32 + lane;

    float acc[8];
    #pragma unroll
    for (int i = 0; i < 8; i++) acc[i] = 0.f;

    int r = r0;
    for (; r + 3 < r1; r += 4) {
        int2 e0 = g_epack[r],     e1 = g_epack[r + 1];
        int2 e2 = g_epack[r + 2], e3 = g_epack[r + 3];
        uint4 u0 = base[(size_t)e0.x * 64 + off];
        uint4 u1 = base[(size_t)e1.x * 64 + off];
        uint4 u2 = base[(size_t)e2.x * 64 + off];
        uint4 u3 = base[(size_t)e3.x * 64 + off];
        float w0 = __int_as_float(e0.y), w1 = __int_as_float(e1.y);
        float w2 = __int_as_float(e2.y), w3 = __int_as_float(e3.y);
        acc8u(acc, u0, w0);
        acc8u(acc, u1, w1);
        acc8u(acc, u2, w2);
        acc8u(acc, u3, w3);
    }
    for (; r < r1; r++) {
        int2 e = g_epack[r];
        float w = __int_as_float(e.y);
        uint4 u = base[(size_t)e.x * 64 + off];
        acc8u(acc, u, w);
    }

    // channel c512 = h*256 + lane*8 + j  ->  t = 4h + lane/8, c0 = (lane%8)*8
    int t  = 4 * h + (lane >> 3);
    int c0 = (lane & 7) * 8;
    float* op = out + ((size_t)t * NN + node) * OUT_F + c0;
    *(float4*)(op)     = make_float4(acc[0], acc[1], acc[2], acc[3]);
    *(float4*)(op + 4) = make_float4(acc[4], acc[5], acc[6], acc[7]);
}

// ---------------- fused fp16 mma GEMM (loop over all t per CTA) ---------------
// smem uint32 (fp16x2) layout, padded lds for conflict-free fragment access:
//   A  128 rows x 48 k2, ld 52  @ 0       (6656)
//   B1 128 n    x 48 k2, ld 52  @ 6656    (6656)
//   B2 64  n    x 64 k2, ld 68  @ 13312   (4352)
//   H  128 rows x 64 k2, ld 68  @ 17664   (8704)
#define OFF_A   0
#define LDA     52
#define OFF_B1  6656
#define LDB1    52
#define OFF_B2  13312
#define LDB2    68
#define OFF_H   17664
#define LDH     68
#define FUSED_WORDS (OFF_H + 128 * LDH)            // 26368 words
#define FUSED_SMEM  (FUSED_WORDS * 4)              // 105472 bytes

__global__ void __launch_bounds__(256, 2)
k_fused_gemm() {
    extern __shared__ uint32_t sm[];
    const int tid  = threadIdx.x;
    const int wid  = tid >> 5;
    const int lane = tid & 31;
    const int gid  = lane >> 2;
    const int tig  = lane & 3;
    const int row0 = blockIdx.x * 128;

    // ---- stage A tile ONCE (fp16x2)
    const uint32_t* ah = (const uint32_t*)g_agg1h;
    for (int e = tid; e < 128 * 48; e += 256) {
        int r = e / 48, k2 = e % 48;
        int gr = row0 + r;
        sm[OFF_A + r * LDA + k2] = (gr < NN) ? ah[gr * 48 + k2] : 0u;
    }

    const int r0 = wid * 16;
    const int rowA = row0 + r0 + gid;
    const int rowB = rowA + 8;

    for (int t = 0; t < TT; t++) {
        __syncthreads();
        {
            const uint32_t* b1 = g_B1h + t * HID_F * 48;
            for (int e = tid; e < HID_F * 48; e += 256)
                sm[OFF_B1 + (e / 48) * LDB1 + (e % 48)] = b1[e];
            const uint32_t* b2 = g_B2h + t * OUT_F * 64;
            for (int e = tid; e < OUT_F * 64; e += 256)
                sm[OFF_B2 + (e >> 6) * LDB2 + (e & 63)] = b2[e];
        }
        __syncthreads();

        // ===== GEMM1: H[128,128] = A[128,96] @ B1, 6 k16-steps =====
        float acc1[16][4];
        #pragma unroll
        for (int j = 0; j < 16; j++)
            #pragma unroll
            for (int i = 0; i < 4; i++) acc1[j][i] = 0.f;

        #pragma unroll
        for (int kb = 0; kb < 6; kb++) {
            const int k2b = kb * 8;
            uint32_t a0 = sm[OFF_A + (r0 + gid)     * LDA + k2b + tig];
            uint32_t a1 = sm[OFF_A + (r0 + gid + 8) * LDA + k2b + tig];
            uint32_t a2 = sm[OFF_A + (r0 + gid)     * LDA + k2b + tig + 4];
            uint32_t a3 = sm[OFF_A + (r0 + gid + 8) * LDA + k2b + tig + 4];
            #pragma unroll
            for (int j = 0; j < 16; j++) {
                uint32_t b0 = sm[OFF_B1 + (j * 8 + gid) * LDB1 + k2b + tig];
                uint32_t b1 = sm[OFF_B1 + (j * 8 + gid) * LDB1 + k2b + tig + 4];
                mma_f16(acc1[j], a0, a1, a2, a3, b0, b1);
            }
        }

        // relu + fp16 pack, store H[row][k2] (warp-private rows)
        #pragma unroll
        for (int j = 0; j < 16; j++) {
            float f0 = acc1[j][0], f1 = acc1[j][1], f2 = acc1[j][2], f3 = acc1[j][3];
            uint32_t uA = pack_h2(f0 > 0.f ? f0 : 0.f, f1 > 0.f ? f1 : 0.f);
            uint32_t uB = pack_h2(f2 > 0.f ? f2 : 0.f, f3 > 0.f ? f3 : 0.f);
            sm[OFF_H + (r0 + gid)     * LDH + 4 * j + tig] = uA;
            sm[OFF_H + (r0 + gid + 8) * LDH + 4 * j + tig] = uB;
        }
        __syncwarp();

        // ===== GEMM2: P[128,64] = H[128,128] @ B2, 8 k16-steps =====
        float acc2[8][4];
        #pragma unroll
        for (int j = 0; j < 8; j++)
            #pragma unroll
            for (int i = 0; i < 4; i++) acc2[j][i] = 0.f;

        #pragma unroll
        for (int kb = 0; kb < 8; kb++) {
            const int k2b = kb * 8;
            uint32_t a0 = sm[OFF_H + (r0 + gid)     * LDH + k2b + tig];
            uint32_t a1 = sm[OFF_H + (r0 + gid + 8) * LDH + k2b + tig];
            uint32_t a2 = sm[OFF_H + (r0 + gid)     * LDH + k2b + tig + 4];
            uint32_t a3 = sm[OFF_H + (r0 + gid + 8) * LDH + k2b + tig + 4];
            #pragma unroll
            for (int j = 0; j < 8; j++) {
                uint32_t b0 = sm[OFF_B2 + (j * 8 + gid) * LDB2 + k2b + tig];
                uint32_t b1 = sm[OFF_B2 + (j * 8 + gid) * LDB2 + k2b + tig + 4];
                mma_f16(acc2[j], a0, a1, a2, a3, b0, b1);
            }
        }

        // ---- epilogue: write p tile as fp16 into g_ph[n][t*64+c]
        if (rowA < NN) {
            __half* p = g_ph + (size_t)rowA * 512 + t * 64;
            #pragma unroll
            for (int j = 0; j < 8; j++)
                *(uint32_t*)(p + j * 8 + 2 * tig) = pack_h2(acc2[j][0], acc2[j][1]);
        }
        if (rowB < NN) {
            __half* p = g_ph + (size_t)rowB * 512 + t * 64;
            #pragma unroll
            for (int j = 0; j < 8; j++)
                *(uint32_t*)(p + j * 8 + 2 * tig) = pack_h2(acc2[j][2], acc2[j][3]);
        }
    }
}

// ---------------- launch ------------------------------------------------------
extern "C" void kernel_launch(void* const* d_in, const int* in_sizes, int n_in,
                              void* d_out, int out_size) {
    (void)in_sizes; (void)n_in; (void)out_size;
    const float* x   = (const float*)d_in[0];
    const float* ew  = (const float*)d_in[1];
    const float* W1  = (const float*)d_in[2];
    const float* W2  = (const float*)d_in[3];
    const float* m1  = (const float*)d_in[4];
    const float* m2  = (const float*)d_in[5];
    const int*   src = (const int*)d_in[6];
    const int*   dst = (const int*)d_in[7];
    float* out = (float*)d_out;

    cudaFuncSetAttribute((const void*)k_fused_gemm,
                         cudaFuncAttributeMaxDynamicSharedMemorySize, FUSED_SMEM);

    // 1. front-end: x->fp16, degree hist, scan sentinel
    k_convert<<<(XW + 255) / 256, 256>>>(x, dst);
    // 2. single-kernel scan -> rowptr/cursor (+ counts re-zeroed)
    k_scan<<<NBLK, SCAN_BLK>>>();
    // 3. CSR scatter + W.*M fp16 prep (absorbed)
    k_scatter<<<(EE + 255) / 256, 256>>>(src, dst, ew, W1, W2, m1, m2);
    // 4. agg1h = spmm(xh)
    k_spmm96<<<(NN * 32 + 255) / 256, 256>>>();
    // 5. fused fp16 mma: p_t = relu(agg1 @ B1_t) @ B2_t
    k_fused_gemm<<<(NN + 127) / 128, 256, FUSED_SMEM>>>();
    // 6. out = spmm(p), 2 warps per node (one per 256-channel half)
    k_spmm_all<<<(NN * 2 * 32 + 255) / 256, 256>>>(out);
}

// round 12
// speedup vs baseline: 1.2258x; 1.0084x over previous
#include <cuda_runtime.h>
#include <cuda_fp16.h>
#include <cstdint>

// Problem constants (fixed by the dataset)
#define NN    50000
#define EE    800000
#define IN_F  96
#define HID_F 128
#define OUT_F 64
#define TT    8

#define SCAN_BLK 512
#define NBLK ((NN + SCAN_BLK - 1) / SCAN_BLK)    // 98

// ---------------- static device scratch (no allocations allowed) -------------
__device__ int      g_counts[NN];      // zero-init at load; re-zeroed by k_scan
__device__ int      g_rowptr[NN + 1];
__device__ int      g_cursor[NN];
__device__ int      g_bsum[NBLK];      // sentinel -1 written by k_convert each call
__device__ int2     g_epack[EE];                            // (src, w-as-bits)
__device__ __half   g_xh[(size_t)NN * IN_F];                // 9.6 MB fp16 x
__device__ __half   g_agg1h[(size_t)NN * IN_F];             // 9.6 MB fp16 agg1
__device__ __half   g_ph[(size_t)NN * TT * OUT_F];          // 51.2 MB, [n][t*64+c]
__device__ uint32_t g_B1h[TT * HID_F * 48];                 // fp16x2 [t][n][k2]
__device__ uint32_t g_B2h[TT * OUT_F * 64];                 // fp16x2 [t][n][k2]

// ---------------- helpers ------------------------------------------------------
__device__ __forceinline__ void mma_f16(float d[4],
                                        uint32_t a0, uint32_t a1, uint32_t a2, uint32_t a3,
                                        uint32_t b0, uint32_t b1) {
    asm volatile("mma.sync.aligned.m16n8k16.row.col.f32.f16.f16.f32 "
        "{%0,%1,%2,%3}, {%4,%5,%6,%7}, {%8,%9}, {%0,%1,%2,%3};"
        : "+f"(d[0]), "+f"(d[1]), "+f"(d[2]), "+f"(d[3])
        : "r"(a0), "r"(a1), "r"(a2), "r"(a3), "r"(b0), "r"(b1));
}
__device__ __forceinline__ uint32_t pack_h2(float a, float b) {
    __half2 h = __float22half2_rn(make_float2(a, b));
    return *(uint32_t*)&h;
}

// ---------------- convert + hist + sentinel (fused front-end) ------------------
#define XW (NN * IN_F / 2)                 // 2,400,000 half2
__global__ void k_convert(const float* __restrict__ x,
                          const int* __restrict__ dst) {
    int i = blockIdx.x * blockDim.x + threadIdx.x;
    if (i < NBLK) g_bsum[i] = -1;                       // sentinel for k_scan
    if (i < EE) atomicAdd(&g_counts[dst[i]], 1);        // degree histogram
    if (i < XW) {
        float2 v = *(const float2*)(x + i * 2);
        *((__half2*)g_xh + i) = __float22half2_rn(v);
    }
}

// ---------------- single-kernel scan (aggregate exchange via sentinel) ---------
__global__ void k_scan() {
    __shared__ int s[SCAN_BLK];
    __shared__ int bs[128];
    int b = blockIdx.x, tid = threadIdx.x;
    int i = b * SCAN_BLK + tid;
    int c = (i < NN) ? g_counts[i] : 0;
    s[tid] = c;
    __syncthreads();
    #pragma unroll
    for (int off = 1; off < SCAN_BLK; off <<= 1) {
        int u = (tid >= off) ? s[tid - off] : 0;
        __syncthreads();
        s[tid] += u;
        __syncthreads();
    }
    if (tid == 0) atomicExch(&g_bsum[b], s[SCAN_BLK - 1]);
    if (tid < 128) {
        int v = 0;
        if (tid < b) {
            int a;
            do { a = atomicAdd(&g_bsum[tid], 0); } while (a == -1);
            v = a;
        }
        bs[tid] = v;
    }
    __syncthreads();
    #pragma unroll
    for (int off = 64; off > 0; off >>= 1) {
        if (tid < off) bs[tid] += bs[tid + off];
        __syncthreads();
    }
    int boff = bs[0];
    if (i < NN) {
        int excl = s[tid] - c + boff;
        g_rowptr[i] = excl;
        g_cursor[i] = excl;
        g_counts[i] = 0;                      // restore invariant for next call
        if (i == NN - 1) g_rowptr[NN] = excl + c;
    }
}

// ---------------- scatter + weight prep (absorbs W.*M conversion) --------------
__global__ void k_scatter(const int* __restrict__ src, const int* __restrict__ dst,
                          const float* __restrict__ ew,
                          const float* __restrict__ W1, const float* __restrict__ W2,
                          const float* __restrict__ M1, const float* __restrict__ M2) {
    int e = blockIdx.x * blockDim.x + threadIdx.x;
    if (e < EE) {
        int d = dst[e];
        int pos = atomicAdd(&g_cursor[d], 1);
        g_epack[pos] = make_int2(src[e], __float_as_int(ew[e]));
    }
    const int S1 = TT * HID_F * 48;        // 49152
    const int S2 = TT * OUT_F * 64;        // 32768
    if (e < S1) {
        int t = e / (HID_F * 48);
        int rem = e % (HID_F * 48);
        int n = rem / 48, k2 = rem % 48;
        int i0 = (2 * k2) * HID_F + n;
        int i1 = i0 + HID_F;
        const float* m = M1 + (size_t)t * IN_F * HID_F;
        g_B1h[e] = pack_h2(W1[i0] * m[i0], W1[i1] * m[i1]);
    }
    if (e < S2) {
        int t = e / (OUT_F * 64);
        int rem = e % (OUT_F * 64);
        int n = rem / 64, k2 = rem % 64;
        int i0 = (2 * k2) * OUT_F + n;
        int i1 = i0 + OUT_F;
        const float* m = M2 + (size_t)t * HID_F * OUT_F;
        g_B2h[e] = pack_h2(W2[i0] * m[i0], W2[i1] * m[i1]);
    }
}

// ---------------- SpMM1: agg1h = spmm(xh), warp per node, LDG.64 x 24 lanes ----
__global__ void k_spmm96() {
    int warp = (blockIdx.x * blockDim.x + threadIdx.x) >> 5;
    int lane = threadIdx.x & 31;
    if (warp >= NN) return;
    int r0 = g_rowptr[warp], r1 = g_rowptr[warp + 1];
    const uint2* xh = (const uint2*)g_xh;     // 24 uint2 (8B) per 192B row
    const bool act = lane < 24;

    float2 A0 = make_float2(0.f, 0.f), A1 = make_float2(0.f, 0.f);
    uint2 z = make_uint2(0u, 0u);
    int r = r0;
    for (; r + 3 < r1; r += 4) {
        int2 e0 = g_epack[r],     e1 = g_epack[r + 1];
        int2 e2 = g_epack[r + 2], e3 = g_epack[r + 3];
        uint2 u0 = act ? xh[e0.x * 24 + lane] : z;
        uint2 u1 = act ? xh[e1.x * 24 + lane] : z;
        uint2 u2 = act ? xh[e2.x * 24 + lane] : z;
        uint2 u3 = act ? xh[e3.x * 24 + lane] : z;
        float w0 = __int_as_float(e0.y), w1 = __int_as_float(e1.y);
        float w2 = __int_as_float(e2.y), w3 = __int_as_float(e3.y);
        float2 f;
        f = __half22float2(*(__half2*)&u0.x); A0.x += w0 * f.x; A0.y += w0 * f.y;
        f = __half22float2(*(__half2*)&u0.y); A1.x += w0 * f.x; A1.y += w0 * f.y;
        f = __half22float2(*(__half2*)&u1.x); A0.x += w1 * f.x; A0.y += w1 * f.y;
        f = __half22float2(*(__half2*)&u1.y); A1.x += w1 * f.x; A1.y += w1 * f.y;
        f = __half22float2(*(__half2*)&u2.x); A0.x += w2 * f.x; A0.y += w2 * f.y;
        f = __half22float2(*(__half2*)&u2.y); A1.x += w2 * f.x; A1.y += w2 * f.y;
        f = __half22float2(*(__half2*)&u3.x); A0.x += w3 * f.x; A0.y += w3 * f.y;
        f = __half22float2(*(__half2*)&u3.y); A1.x += w3 * f.x; A1.y += w3 * f.y;
    }
    for (; r < r1; r++) {
        int2 e = g_epack[r];
        float w = __int_as_float(e.y);
        uint2 u = act ? xh[e.x * 24 + lane] : z;
        float2 f;
        f = __half22float2(*(__half2*)&u.x); A0.x += w * f.x; A0.y += w * f.y;
        f = __half22float2(*(__half2*)&u.y); A1.x += w * f.x; A1.y += w * f.y;
    }
    if (act) {
        uint2 o = make_uint2(pack_h2(A0.x, A0.y), pack_h2(A1.x, A1.y));
        ((uint2*)g_agg1h)[(size_t)warp * 24 + lane] = o;
    }
}

// ---------------- SpMM2: out[t,n,:] = spmm(p_t), 2 warps per node --------------
__device__ __forceinline__ void acc8u(float acc[8], uint4 u, float w) {
    const __half2* h = (const __half2*)&u;
    #pragma unroll
    for (int q = 0; q < 4; q++) {
        float2 f = __half22float2(h[q]);
        acc[2 * q]     += w * f.x;
        acc[2 * q + 1] += w * f.y;
    }
}

__global__ void k_spmm_all(float* __restrict__ out) {
    int gw   = (blockIdx.x * blockDim.x + threadIdx.x) >> 5;  // global warp
    int node = gw >> 1;
    int h    = gw & 1;                                         // channel half
    int lane = threadIdx.x & 31;
    if (node >= NN) return;
    int r0 = g_rowptr[node], r1 = g_rowptr[node + 1];

    const uint4* base = (const uint4*)g_ph;
    const int off = h * 32 + lane;

    float acc[8];
    #pragma unroll
    for (int i = 0; i < 8; i++) acc[i] = 0.f;

    int r = r0;
    for (; r + 3 < r1; r += 4) {
        int2 e0 = g_epack[r],     e1 = g_epack[r + 1];
        int2 e2 = g_epack[r + 2], e3 = g_epack[r + 3];
        uint4 u0 = base[(size_t)e0.x * 64 + off];
        uint4 u1 = base[(size_t)e1.x * 64 + off];
        uint4 u2 = base[(size_t)e2.x * 64 + off];
        uint4 u3 = base[(size_t)e3.x * 64 + off];
        float w0 = __int_as_float(e0.y), w1 = __int_as_float(e1.y);
        float w2 = __int_as_float(e2.y), w3 = __int_as_float(e3.y);
        acc8u(acc, u0, w0);
        acc8u(acc, u1, w1);
        acc8u(acc, u2, w2);
        acc8u(acc, u3, w3);
    }
    for (; r < r1; r++) {
        int2 e = g_epack[r];
        float w = __int_as_float(e.y);
        uint4 u = base[(size_t)e.x * 64 + off];
        acc8u(acc, u, w);
    }

    int t  = 4 * h + (lane >> 3);
    int c0 = (lane & 7) * 8;
    float* op = out + ((size_t)t * NN + node) * OUT_F + c0;
    *(float4*)(op)     = make_float4(acc[0], acc[1], acc[2], acc[3]);
    *(float4*)(op + 4) = make_float4(acc[4], acc[5], acc[6], acc[7]);
}

// ---------------- fused fp16 mma GEMM (4 samples per CTA, grid.y=2) -----------
// smem uint32 (fp16x2) layout, padded lds for conflict-free fragment access:
//   A  128 rows x 48 k2, ld 52  @ 0       (6656)
//   B1 128 n    x 48 k2, ld 52  @ 6656    (6656)
//   B2 64  n    x 64 k2, ld 68  @ 13312   (4352)
//   H  128 rows x 64 k2, ld 68  @ 17664   (8704)
#define OFF_A   0
#define LDA     52
#define OFF_B1  6656
#define LDB1    52
#define OFF_B2  13312
#define LDB2    68
#define OFF_H   17664
#define LDH     68
#define FUSED_WORDS (OFF_H + 128 * LDH)            // 26368 words
#define FUSED_SMEM  (FUSED_WORDS * 4)              // 105472 bytes

__global__ void __launch_bounds__(256, 2)
k_fused_gemm() {
    extern __shared__ uint32_t sm[];
    const int tid  = threadIdx.x;
    const int wid  = tid >> 5;
    const int lane = tid & 31;
    const int gid  = lane >> 2;
    const int tig  = lane & 3;
    const int row0 = blockIdx.x * 128;
    const int tbase = blockIdx.y * 4;              // 4 MC samples per CTA

    // ---- stage A tile ONCE (fp16x2)
    const uint32_t* ah = (const uint32_t*)g_agg1h;
    for (int e = tid; e < 128 * 48; e += 256) {
        int r = e / 48, k2 = e % 48;
        int gr = row0 + r;
        sm[OFF_A + r * LDA + k2] = (gr < NN) ? ah[gr * 48 + k2] : 0u;
    }

    const int r0 = wid * 16;
    const int rowA = row0 + r0 + gid;
    const int rowB = rowA + 8;

    for (int ti = 0; ti < 4; ti++) {
        const int t = tbase + ti;
        __syncthreads();
        {
            const uint32_t* b1 = g_B1h + t * HID_F * 48;
            for (int e = tid; e < HID_F * 48; e += 256)
                sm[OFF_B1 + (e / 48) * LDB1 + (e % 48)] = b1[e];
            const uint32_t* b2 = g_B2h + t * OUT_F * 64;
            for (int e = tid; e < OUT_F * 64; e += 256)
                sm[OFF_B2 + (e >> 6) * LDB2 + (e & 63)] = b2[e];
        }
        __syncthreads();

        // ===== GEMM1: H[128,128] = A[128,96] @ B1, 6 k16-steps =====
        float acc1[16][4];
        #pragma unroll
        for (int j = 0; j < 16; j++)
            #pragma unroll
            for (int i = 0; i < 4; i++) acc1[j][i] = 0.f;

        #pragma unroll
        for (int kb = 0; kb < 6; kb++) {
            const int k2b = kb * 8;
            uint32_t a0 = sm[OFF_A + (r0 + gid)     * LDA + k2b + tig];
            uint32_t a1 = sm[OFF_A + (r0 + gid + 8) * LDA + k2b + tig];
            uint32_t a2 = sm[OFF_A + (r0 + gid)     * LDA + k2b + tig + 4];
            uint32_t a3 = sm[OFF_A + (r0 + gid + 8) * LDA + k2b + tig + 4];
            #pragma unroll
            for (int j = 0; j < 16; j++) {
                uint32_t b0 = sm[OFF_B1 + (j * 8 + gid) * LDB1 + k2b + tig];
                uint32_t b1 = sm[OFF_B1 + (j * 8 + gid) * LDB1 + k2b + tig + 4];
                mma_f16(acc1[j], a0, a1, a2, a3, b0, b1);
            }
        }

        // relu + fp16 pack, store H[row][k2] (warp-private rows)
        #pragma unroll
        for (int j = 0; j < 16; j++) {
            float f0 = acc1[j][0], f1 = acc1[j][1], f2 = acc1[j][2], f3 = acc1[j][3];
            uint32_t uA = pack_h2(f0 > 0.f ? f0 : 0.f, f1 > 0.f ? f1 : 0.f);
            uint32_t uB = pack_h2(f2 > 0.f ? f2 : 0.f, f3 > 0.f ? f3 : 0.f);
            sm[OFF_H + (r0 + gid)     * LDH + 4 * j + tig] = uA;
            sm[OFF_H + (r0 + gid + 8) * LDH + 4 * j + tig] = uB;
        }
        __syncwarp();

        // ===== GEMM2: P[128,64] = H[128,128] @ B2, 8 k16-steps =====
        float acc2[8][4];
        #pragma unroll
        for (int j = 0; j < 8; j++)
            #pragma unroll
            for (int i = 0; i < 4; i++) acc2[j][i] = 0.f;

        #pragma unroll
        for (int kb = 0; kb < 8; kb++) {
            const int k2b = kb * 8;
            uint32_t a0 = sm[OFF_H + (r0 + gid)     * LDH + k2b + tig];
            uint32_t a1 = sm[OFF_H + (r0 + gid + 8) * LDH + k2b + tig];
            uint32_t a2 = sm[OFF_H + (r0 + gid)     * LDH + k2b + tig + 4];
            uint32_t a3 = sm[OFF_H + (r0 + gid + 8) * LDH + k2b + tig + 4];
            #pragma unroll
            for (int j = 0; j < 8; j++) {
                uint32_t b0 = sm[OFF_B2 + (j * 8 + gid) * LDB2 + k2b + tig];
                uint32_t b1 = sm[OFF_B2 + (j * 8 + gid) * LDB2 + k2b + tig + 4];
                mma_f16(acc2[j], a0, a1, a2, a3, b0, b1);
            }
        }

        // ---- epilogue: write p tile as fp16 into g_ph[n][t*64+c]
        if (rowA < NN) {
            __half* p = g_ph + (size_t)rowA * 512 + t * 64;
            #pragma unroll
            for (int j = 0; j < 8; j++)
                *(uint32_t*)(p + j * 8 + 2 * tig) = pack_h2(acc2[j][0], acc2[j][1]);
        }
        if (rowB < NN) {
            __half* p = g_ph + (size_t)rowB * 512 + t * 64;
            #pragma unroll
            for (int j = 0; j < 8; j++)
                *(uint32_t*)(p + j * 8 + 2 * tig) = pack_h2(acc2[j][2], acc2[j][3]);
        }
    }
}

// ---------------- launch ------------------------------------------------------
extern "C" void kernel_launch(void* const* d_in, const int* in_sizes, int n_in,
                              void* d_out, int out_size) {
    (void)in_sizes; (void)n_in; (void)out_size;
    const float* x   = (const float*)d_in[0];
    const float* ew  = (const float*)d_in[1];
    const float* W1  = (const float*)d_in[2];
    const float* W2  = (const float*)d_in[3];
    const float* m1  = (const float*)d_in[4];
    const float* m2  = (const float*)d_in[5];
    const int*   src = (const int*)d_in[6];
    const int*   dst = (const int*)d_in[7];
    float* out = (float*)d_out;

    cudaFuncSetAttribute((const void*)k_fused_gemm,
                         cudaFuncAttributeMaxDynamicSharedMemorySize, FUSED_SMEM);

    // 1. front-end: x->fp16, degree hist, scan sentinel
    k_convert<<<(XW + 255) / 256, 256>>>(x, dst);
    // 2. single-kernel scan -> rowptr/cursor (+ counts re-zeroed)
    k_scan<<<NBLK, SCAN_BLK>>>();
    // 3. CSR scatter + W.*M fp16 prep (absorbed)
    k_scatter<<<(EE + 255) / 256, 256>>>(src, dst, ew, W1, W2, m1, m2);
    // 4. agg1h = spmm(xh)
    k_spmm96<<<(NN * 32 + 255) / 256, 256>>>();
    // 5. fused fp16 mma, 4 samples per CTA, grid.y=2 (wave-quantization fix)
    dim3 gf((NN + 127) / 128, 2);
    k_fused_gemm<<<gf, 256, FUSED_SMEM>>>();
    // 6. out = spmm(p), 2 warps per node (one per 256-channel half)
    k_spmm_all<<<(NN * 2 * 32 + 255) / 256, 256>>>(out);
}

// round 13
// speedup vs baseline: 1.2818x; 1.0457x over previous
#include <cuda_runtime.h>
#include <cuda_fp16.h>
#include <cstdint>

// Problem constants (fixed by the dataset)
#define NN    50000
#define EE    800000
#define IN_F  96
#define HID_F 128
#define OUT_F 64
#define TT    8

#define SCAN_BLK 512
#define NBLK ((NN + SCAN_BLK - 1) / SCAN_BLK)    // 98

// ---------------- static device scratch (no allocations allowed) -------------
__device__ int      g_counts[NN];      // zero-init at load; re-zeroed by k_scan
__device__ int      g_rowptr[NN + 1];
__device__ int      g_cursor[NN];
__device__ int      g_bsum[NBLK];      // sentinel -1 written by k_convert each call
__device__ int2     g_epack[EE];                            // (src, w-as-bits)
__device__ __half   g_xh[(size_t)NN * IN_F];                // 9.6 MB fp16 x
__device__ __half   g_agg1h[(size_t)NN * IN_F];             // 9.6 MB fp16 agg1
__device__ __half   g_ph[(size_t)NN * TT * OUT_F];          // 51.2 MB, [n][t*64+c]
__device__ uint32_t g_B1h[TT * HID_F * 48];                 // fp16x2 [t][n][k2]
__device__ uint32_t g_B2h[TT * OUT_F * 64];                 // fp16x2 [t][n][k2]

// ---------------- helpers ------------------------------------------------------
__device__ __forceinline__ void mma_f16(float d[4],
                                        uint32_t a0, uint32_t a1, uint32_t a2, uint32_t a3,
                                        uint32_t b0, uint32_t b1) {
    asm volatile("mma.sync.aligned.m16n8k16.row.col.f32.f16.f16.f32 "
        "{%0,%1,%2,%3}, {%4,%5,%6,%7}, {%8,%9}, {%0,%1,%2,%3};"
        : "+f"(d[0]), "+f"(d[1]), "+f"(d[2]), "+f"(d[3])
        : "r"(a0), "r"(a1), "r"(a2), "r"(a3), "r"(b0), "r"(b1));
}
__device__ __forceinline__ uint32_t pack_h2(float a, float b) {
    __half2 h = __float22half2_rn(make_float2(a, b));
    return *(uint32_t*)&h;
}

// ---------------- convert + hist + sentinel (fused front-end) ------------------
#define XW4 (NN * IN_F / 4)                // 1,200,000 float4 granules (> EE ok)
__global__ void k_convert(const float* __restrict__ x,
                          const int* __restrict__ dst) {
    int i = blockIdx.x * blockDim.x + threadIdx.x;
    if (i < NBLK) g_bsum[i] = -1;                       // sentinel for k_scan
    if (i < EE) atomicAdd(&g_counts[dst[i]], 1);        // degree histogram
    if (i < XW4) {
        float4 v = ((const float4*)x)[i];
        uint2 o = make_uint2(pack_h2(v.x, v.y), pack_h2(v.z, v.w));
        ((uint2*)g_xh)[i] = o;
    }
}

// ---------------- single-kernel scan (aggregate exchange via sentinel) ---------
__global__ void k_scan() {
    __shared__ int s[SCAN_BLK];
    __shared__ int bs[128];
    int b = blockIdx.x, tid = threadIdx.x;
    int i = b * SCAN_BLK + tid;
    int c = (i < NN) ? g_counts[i] : 0;
    s[tid] = c;
    __syncthreads();
    #pragma unroll
    for (int off = 1; off < SCAN_BLK; off <<= 1) {
        int u = (tid >= off) ? s[tid - off] : 0;
        __syncthreads();
        s[tid] += u;
        __syncthreads();
    }
    if (tid == 0) atomicExch(&g_bsum[b], s[SCAN_BLK - 1]);
    if (tid < 128) {
        int v = 0;
        if (tid < b) {
            int a;
            do { a = atomicAdd(&g_bsum[tid], 0); } while (a == -1);
            v = a;
        }
        bs[tid] = v;
    }
    __syncthreads();
    #pragma unroll
    for (int off = 64; off > 0; off >>= 1) {
        if (tid < off) bs[tid] += bs[tid + off];
        __syncthreads();
    }
    int boff = bs[0];
    if (i < NN) {
        int excl = s[tid] - c + boff;
        g_rowptr[i] = excl;
        g_cursor[i] = excl;
        g_counts[i] = 0;                      // restore invariant for next call
        if (i == NN - 1) g_rowptr[NN] = excl + c;
    }
}

// ---------------- scatter + weight prep (absorbs W.*M conversion) --------------
__global__ void k_scatter(const int* __restrict__ src, const int* __restrict__ dst,
                          const float* __restrict__ ew,
                          const float* __restrict__ W1, const float* __restrict__ W2,
                          const float* __restrict__ M1, const float* __restrict__ M2) {
    int e = blockIdx.x * blockDim.x + threadIdx.x;
    if (e < EE) {
        int d = dst[e];
        int pos = atomicAdd(&g_cursor[d], 1);
        g_epack[pos] = make_int2(src[e], __float_as_int(ew[e]));
    }
    const int S1 = TT * HID_F * 48;        // 49152
    const int S2 = TT * OUT_F * 64;        // 32768
    if (e < S1) {
        int t = e / (HID_F * 48);
        int rem = e % (HID_F * 48);
        int n = rem / 48, k2 = rem % 48;
        int i0 = (2 * k2) * HID_F + n;
        int i1 = i0 + HID_F;
        const float* m = M1 + (size_t)t * IN_F * HID_F;
        g_B1h[e] = pack_h2(W1[i0] * m[i0], W1[i1] * m[i1]);
    }
    if (e < S2) {
        int t = e / (OUT_F * 64);
        int rem = e % (OUT_F * 64);
        int n = rem / 64, k2 = rem % 64;
        int i0 = (2 * k2) * OUT_F + n;
        int i1 = i0 + OUT_F;
        const float* m = M2 + (size_t)t * HID_F * OUT_F;
        g_B2h[e] = pack_h2(W2[i0] * m[i0], W2[i1] * m[i1]);
    }
}

// ---------------- SpMM1: agg1h = spmm(xh), warp per node, LDG.64 x 24 lanes ----
__global__ void k_spmm96() {
    int warp = (blockIdx.x * blockDim.x + threadIdx.x) >> 5;
    int lane = threadIdx.x & 31;
    if (warp >= NN) return;
    int r0 = g_rowptr[warp], r1 = g_rowptr[warp + 1];
    const uint2* xh = (const uint2*)g_xh;     // 24 uint2 (8B) per 192B row
    const bool act = lane < 24;

    float2 A0 = make_float2(0.f, 0.f), A1 = make_float2(0.f, 0.f);
    uint2 z = make_uint2(0u, 0u);
    int r = r0;
    for (; r + 3 < r1; r += 4) {
        int2 e0 = g_epack[r],     e1 = g_epack[r + 1];
        int2 e2 = g_epack[r + 2], e3 = g_epack[r + 3];
        uint2 u0 = act ? xh[e0.x * 24 + lane] : z;
        uint2 u1 = act ? xh[e1.x * 24 + lane] : z;
        uint2 u2 = act ? xh[e2.x * 24 + lane] : z;
        uint2 u3 = act ? xh[e3.x * 24 + lane] : z;
        float w0 = __int_as_float(e0.y), w1 = __int_as_float(e1.y);
        float w2 = __int_as_float(e2.y), w3 = __int_as_float(e3.y);
        float2 f;
        f = __half22float2(*(__half2*)&u0.x); A0.x += w0 * f.x; A0.y += w0 * f.y;
        f = __half22float2(*(__half2*)&u0.y); A1.x += w0 * f.x; A1.y += w0 * f.y;
        f = __half22float2(*(__half2*)&u1.x); A0.x += w1 * f.x; A0.y += w1 * f.y;
        f = __half22float2(*(__half2*)&u1.y); A1.x += w1 * f.x; A1.y += w1 * f.y;
        f = __half22float2(*(__half2*)&u2.x); A0.x += w2 * f.x; A0.y += w2 * f.y;
        f = __half22float2(*(__half2*)&u2.y); A1.x += w2 * f.x; A1.y += w2 * f.y;
        f = __half22float2(*(__half2*)&u3.x); A0.x += w3 * f.x; A0.y += w3 * f.y;
        f = __half22float2(*(__half2*)&u3.y); A1.x += w3 * f.x; A1.y += w3 * f.y;
    }
    if (r + 1 < r1) {                       // 2-batch tail
        int2 e0 = g_epack[r], e1 = g_epack[r + 1];
        uint2 u0 = act ? xh[e0.x * 24 + lane] : z;
        uint2 u1 = act ? xh[e1.x * 24 + lane] : z;
        float w0 = __int_as_float(e0.y), w1 = __int_as_float(e1.y);
        float2 f;
        f = __half22float2(*(__half2*)&u0.x); A0.x += w0 * f.x; A0.y += w0 * f.y;
        f = __half22float2(*(__half2*)&u0.y); A1.x += w0 * f.x; A1.y += w0 * f.y;
        f = __half22float2(*(__half2*)&u1.x); A0.x += w1 * f.x; A0.y += w1 * f.y;
        f = __half22float2(*(__half2*)&u1.y); A1.x += w1 * f.x; A1.y += w1 * f.y;
        r += 2;
    }
    if (r < r1) {
        int2 e = g_epack[r];
        float w = __int_as_float(e.y);
        uint2 u = act ? xh[e.x * 24 + lane] : z;
        float2 f;
        f = __half22float2(*(__half2*)&u.x); A0.x += w * f.x; A0.y += w * f.y;
        f = __half22float2(*(__half2*)&u.y); A1.x += w * f.x; A1.y += w * f.y;
    }
    if (act) {
        uint2 o = make_uint2(pack_h2(A0.x, A0.y), pack_h2(A1.x, A1.y));
        ((uint2*)g_agg1h)[(size_t)warp * 24 + lane] = o;
    }
}

// ---------------- SpMM2: out[t,n,:] = spmm(p_t), 2 warps per node, unroll 8 ----
__device__ __forceinline__ void acc8u(float acc[8], uint4 u, float w) {
    const __half2* h = (const __half2*)&u;
    #pragma unroll
    for (int q = 0; q < 4; q++) {
        float2 f = __half22float2(h[q]);
        acc[2 * q]     += w * f.x;
        acc[2 * q + 1] += w * f.y;
    }
}

__global__ void k_spmm_all(float* __restrict__ out) {
    int gw   = (blockIdx.x * blockDim.x + threadIdx.x) >> 5;  // global warp
    int node = gw >> 1;
    int h    = gw & 1;                                         // channel half
    int lane = threadIdx.x & 31;
    if (node >= NN) return;
    int r0 = g_rowptr[node], r1 = g_rowptr[node + 1];

    const uint4* base = (const uint4*)g_ph;
    const int off = h * 32 + lane;

    float acc[8];
    #pragma unroll
    for (int i = 0; i < 8; i++) acc[i] = 0.f;

    int r = r0;
    for (; r + 7 < r1; r += 8) {                // 8-deep MLP main loop
        int2 e[8];
        #pragma unroll
        for (int q = 0; q < 8; q++) e[q] = g_epack[r + q];
        uint4 u[8];
        #pragma unroll
        for (int q = 0; q < 8; q++) u[q] = base[(size_t)e[q].x * 64 + off];
        #pragma unroll
        for (int q = 0; q < 8; q++) acc8u(acc, u[q], __int_as_float(e[q].y));
    }
    if (r + 3 < r1) {                           // 4-batch tail
        int2 e[4];
        #pragma unroll
        for (int q = 0; q < 4; q++) e[q] = g_epack[r + q];
        uint4 u[4];
        #pragma unroll
        for (int q = 0; q < 4; q++) u[q] = base[(size_t)e[q].x * 64 + off];
        #pragma unroll
        for (int q = 0; q < 4; q++) acc8u(acc, u[q], __int_as_float(e[q].y));
        r += 4;
    }
    if (r + 1 < r1) {                           // 2-batch tail
        int2 e0 = g_epack[r], e1 = g_epack[r + 1];
        uint4 u0 = base[(size_t)e0.x * 64 + off];
        uint4 u1 = base[(size_t)e1.x * 64 + off];
        acc8u(acc, u0, __int_as_float(e0.y));
        acc8u(acc, u1, __int_as_float(e1.y));
        r += 2;
    }
    if (r < r1) {
        int2 e = g_epack[r];
        uint4 u = base[(size_t)e.x * 64 + off];
        acc8u(acc, u, __int_as_float(e.y));
    }

    int t  = 4 * h + (lane >> 3);
    int c0 = (lane & 7) * 8;
    float* op = out + ((size_t)t * NN + node) * OUT_F + c0;
    *(float4*)(op)     = make_float4(acc[0], acc[1], acc[2], acc[3]);
    *(float4*)(op + 4) = make_float4(acc[4], acc[5], acc[6], acc[7]);
}

// ---------------- fused fp16 mma GEMM (4 samples per CTA, grid.y=2) -----------
// smem uint32 (fp16x2) layout, padded lds for conflict-free fragment access:
//   A  128 rows x 48 k2, ld 52  @ 0       (6656)
//   B1 128 n    x 48 k2, ld 52  @ 6656    (6656)
//   B2 64  n    x 64 k2, ld 68  @ 13312   (4352)
//   H  128 rows x 64 k2, ld 68  @ 17664   (8704)
#define OFF_A   0
#define LDA     52
#define OFF_B1  6656
#define LDB1    52
#define OFF_B2  13312
#define LDB2    68
#define OFF_H   17664
#define LDH     68
#define FUSED_WORDS (OFF_H + 128 * LDH)            // 26368 words
#define FUSED_SMEM  (FUSED_WORDS * 4)              // 105472 bytes

__global__ void __launch_bounds__(256, 2)
k_fused_gemm() {
    extern __shared__ uint32_t sm[];
    const int tid  = threadIdx.x;
    const int wid  = tid >> 5;
    const int lane = tid & 31;
    const int gid  = lane >> 2;
    const int tig  = lane & 3;
    const int row0 = blockIdx.x * 128;
    const int tbase = blockIdx.y * 4;              // 4 MC samples per CTA

    // ---- stage A tile ONCE (fp16x2)
    const uint32_t* ah = (const uint32_t*)g_agg1h;
    for (int e = tid; e < 128 * 48; e += 256) {
        int r = e / 48, k2 = e % 48;
        int gr = row0 + r;
        sm[OFF_A + r * LDA + k2] = (gr < NN) ? ah[gr * 48 + k2] : 0u;
    }

    const int r0 = wid * 16;
    const int rowA = row0 + r0 + gid;
    const int rowB = rowA + 8;

    for (int ti = 0; ti < 4; ti++) {
        const int t = tbase + ti;
        __syncthreads();
        {
            const uint32_t* b1 = g_B1h + t * HID_F * 48;
            for (int e = tid; e < HID_F * 48; e += 256)
                sm[OFF_B1 + (e / 48) * LDB1 + (e % 48)] = b1[e];
            const uint32_t* b2 = g_B2h + t * OUT_F * 64;
            for (int e = tid; e < OUT_F * 64; e += 256)
                sm[OFF_B2 + (e >> 6) * LDB2 + (e & 63)] = b2[e];
        }
        __syncthreads();

        // ===== GEMM1: H[128,128] = A[128,96] @ B1, 6 k16-steps =====
        float acc1[16][4];
        #pragma unroll
        for (int j = 0; j < 16; j++)
            #pragma unroll
            for (int i = 0; i < 4; i++) acc1[j][i] = 0.f;

        #pragma unroll
        for (int kb = 0; kb < 6; kb++) {
            const int k2b = kb * 8;
            uint32_t a0 = sm[OFF_A + (r0 + gid)     * LDA + k2b + tig];
            uint32_t a1 = sm[OFF_A + (r0 + gid + 8) * LDA + k2b + tig];
            uint32_t a2 = sm[OFF_A + (r0 + gid)     * LDA + k2b + tig + 4];
            uint32_t a3 = sm[OFF_A + (r0 + gid + 8) * LDA + k2b + tig + 4];
            #pragma unroll
            for (int j = 0; j < 16; j++) {
                uint32_t b0 = sm[OFF_B1 + (j * 8 + gid) * LDB1 + k2b + tig];
                uint32_t b1 = sm[OFF_B1 + (j * 8 + gid) * LDB1 + k2b + tig + 4];
                mma_f16(acc1[j], a0, a1, a2, a3, b0, b1);
            }
        }

        // relu + fp16 pack, store H[row][k2] (warp-private rows)
        #pragma unroll
        for (int j = 0; j < 16; j++) {
            float f0 = acc1[j][0], f1 = acc1[j][1], f2 = acc1[j][2], f3 = acc1[j][3];
            uint32_t uA = pack_h2(f0 > 0.f ? f0 : 0.f, f1 > 0.f ? f1 : 0.f);
            uint32_t uB = pack_h2(f2 > 0.f ? f2 : 0.f, f3 > 0.f ? f3 : 0.f);
            sm[OFF_H + (r0 + gid)     * LDH + 4 * j + tig] = uA;
            sm[OFF_H + (r0 + gid + 8) * LDH + 4 * j + tig] = uB;
        }
        __syncwarp();

        // ===== GEMM2: P[128,64] = H[128,128] @ B2, 8 k16-steps =====
        float acc2[8][4];
        #pragma unroll
        for (int j = 0; j < 8; j++)
            #pragma unroll
            for (int i = 0; i < 4; i++) acc2[j][i] = 0.f;

        #pragma unroll
        for (int kb = 0; kb < 8; kb++) {
            const int k2b = kb * 8;
            uint32_t a0 = sm[OFF_H + (r0 + gid)     * LDH + k2b + tig];
            uint32_t a1 = sm[OFF_H + (r0 + gid + 8) * LDH + k2b + tig];
            uint32_t a2 = sm[OFF_H + (r0 + gid)     * LDH + k2b + tig + 4];
            uint32_t a3 = sm[OFF_H + (r0 + gid + 8) * LDH + k2b + tig + 4];
            #pragma unroll
            for (int j = 0; j < 8; j++) {
                uint32_t b0 = sm[OFF_B2 + (j * 8 + gid) * LDB2 + k2b + tig];
                uint32_t b1 = sm[OFF_B2 + (j * 8 + gid) * LDB2 + k2b + tig + 4];
                mma_f16(acc2[j], a0, a1, a2, a3, b0, b1);
            }
        }

        // ---- epilogue: write p tile as fp16 into g_ph[n][t*64+c]
        if (rowA < NN) {
            __half* p = g_ph + (size_t)rowA * 512 + t * 64;
            #pragma unroll
            for (int j = 0; j < 8; j++)
                *(uint32_t*)(p + j * 8 + 2 * tig) = pack_h2(acc2[j][0], acc2[j][1]);
        }
        if (rowB < NN) {
            __half* p = g_ph + (size_t)rowB * 512 + t * 64;
            #pragma unroll
            for (int j = 0; j < 8; j++)
                *(uint32_t*)(p + j * 8 + 2 * tig) = pack_h2(acc2[j][2], acc2[j][3]);
        }
    }
}

// ---------------- launch ------------------------------------------------------
extern "C" void kernel_launch(void* const* d_in, const int* in_sizes, int n_in,
                              void* d_out, int out_size) {
    (void)in_sizes; (void)n_in; (void)out_size;
    const float* x   = (const float*)d_in[0];
    const float* ew  = (const float*)d_in[1];
    const float* W1  = (const float*)d_in[2];
    const float* W2  = (const float*)d_in[3];
    const float* m1  = (const float*)d_in[4];
    const float* m2  = (const float*)d_in[5];
    const int*   src = (const int*)d_in[6];
    const int*   dst = (const int*)d_in[7];
    float* out = (float*)d_out;

    cudaFuncSetAttribute((const void*)k_fused_gemm,
                         cudaFuncAttributeMaxDynamicSharedMemorySize, FUSED_SMEM);

    // 1. front-end: x->fp16 (float4), degree hist, scan sentinel
    k_convert<<<(XW4 + 255) / 256, 256>>>(x, dst);
    // 2. single-kernel scan -> rowptr/cursor (+ counts re-zeroed)
    k_scan<<<NBLK, SCAN_BLK>>>();
    // 3. CSR scatter + W.*M fp16 prep (absorbed)
    k_scatter<<<(EE + 255) / 256, 256>>>(src, dst, ew, W1, W2, m1, m2);
    // 4. agg1h = spmm(xh)
    k_spmm96<<<(NN * 32 + 255) / 256, 256>>>();
    // 5. fused fp16 mma, 4 samples per CTA, grid.y=2 (wave-quantization fix)
    dim3 gf((NN + 127) / 128, 2);
    k_fused_gemm<<<gf, 256, FUSED_SMEM>>>();
    // 6. out = spmm(p), 2 warps per node, 8-deep gather pipeline
    k_spmm_all<<<(NN * 2 * 32 + 255) / 256, 256>>>(out);
}